// round 7
// baseline (speedup 1.0000x reference)
#include <cuda_runtime.h>
#include <cuda_bf16.h>
#include <math.h>
#include <stdint.h>

// ---------------- problem constants ----------------
#define B_      64
#define EVI_    5
#define SEQS_   (B_ * EVI_)          // 320
#define L_      256
#define D_      768
#define D2_     (D_ / 2)             // 384 u32 per row
#define WORDS_  32
#define TPW_    4
#define NN_     (SEQS_ * WORDS_)     // 10240 nodes
#define EE_     (NN_ * 16)           // 163840 edges
#define R_      4
#define DOUT_   768
#define LH_     1024
#define NC_     3
#define KTOT_   (5 * D_)             // 3840 fused K
#define NR_     (NN_ * R_)           // 40960 segments

// ---------------- scratch (device globals; no allocs allowed) ----------------
__device__ float    g_x   [(size_t)NN_ * D_];        // x0 / x2 (fp32)
__device__ float    g_acc [(size_t)NN_ * D_];        // x1 (fp32)
__device__ uint32_t g_hhi [(size_t)R_ * NN_ * D2_];  // split(h) hi, k-pair packed
__device__ uint32_t g_hlo [(size_t)R_ * NN_ * D2_];
__device__ uint32_t g_xhi [(size_t)NN_ * D2_];       // split(x0)
__device__ uint32_t g_xlo [(size_t)NN_ * D2_];
__device__ uint32_t g_yhi [(size_t)NN_ * D2_];       // split(x1)
__device__ uint32_t g_ylo [(size_t)NN_ * D2_];
__device__ uint32_t g_whi [(size_t)KTOT_ * D2_];     // split(Wcat) [k][n-pairs]
__device__ uint32_t g_wlo [(size_t)KTOT_ * D2_];
__device__ int      g_cnt [NR_];
__device__ int      g_off [NR_ + 1];
__device__ int      g_cur [NR_];
__device__ int      g_elist[EE_];
__device__ float    g_ev  [SEQS_ * 2 * DOUT_];
__device__ float    g_attin[SEQS_ * (D_ + 2 * DOUT_)];
__device__ float    g_hatt[SEQS_ * DOUT_];
__device__ float    g_p   [SEQS_];
__device__ float    g_a   [SEQS_];
__device__ float    g_rep [B_ * (2 * DOUT_ + D_)];
__device__ float    g_hid [B_ * LH_];

// ---------------- small device helpers ----------------
__device__ __forceinline__ uint32_t smem_u32(const void* p) {
    uint32_t a;
    asm("{ .reg .u64 t; cvta.to.shared.u64 t, %1; cvt.u32.u64 %0, t; }" : "=r"(a) : "l"(p));
    return a;
}
__device__ __forceinline__ uint32_t pack2(float lo, float hi) {
    uint32_t r;
    asm("cvt.rn.bf16x2.f32 %0, %1, %2;" : "=r"(r) : "f"(hi), "f"(lo));
    return r;
}
__device__ __forceinline__ void split2(float v0, float v1, uint32_t& h, uint32_t& l) {
    h = pack2(v0, v1);
    l = pack2(v0 - __uint_as_float(h << 16), v1 - __uint_as_float(h & 0xFFFF0000u));
}
__device__ __forceinline__ void mma16816(float* c, const uint32_t* a, const uint32_t* b) {
    asm volatile("mma.sync.aligned.m16n8k16.row.col.f32.bf16.bf16.f32 "
                 "{%0,%1,%2,%3}, {%4,%5,%6,%7}, {%8,%9}, {%0,%1,%2,%3};"
                 : "+f"(c[0]), "+f"(c[1]), "+f"(c[2]), "+f"(c[3])
                 : "r"(a[0]), "r"(a[1]), "r"(a[2]), "r"(a[3]), "r"(b[0]), "r"(b[1]));
}
__device__ __forceinline__ void ldmx4(uint32_t* r, uint32_t addr) {
    asm volatile("ldmatrix.sync.aligned.m8n8.x4.shared.b16 {%0,%1,%2,%3}, [%4];"
                 : "=r"(r[0]), "=r"(r[1]), "=r"(r[2]), "=r"(r[3]) : "r"(addr));
}
__device__ __forceinline__ void ldmx4t(uint32_t* r, uint32_t addr) {
    asm volatile("ldmatrix.sync.aligned.m8n8.x4.trans.shared.b16 {%0,%1,%2,%3}, [%4];"
                 : "=r"(r[0]), "=r"(r[1]), "=r"(r[2]), "=r"(r[3]) : "r"(addr));
}
__device__ __forceinline__ void cp16(uint32_t dst, const void* src) {
    asm volatile("cp.async.cg.shared.global [%0], [%1], 16;" :: "r"(dst), "l"(src));
}

// ---------------- utility kernels ----------------
__global__ void zero4_kernel(float4* p, long long n4) {
    long long t = (long long)blockIdx.x * blockDim.x + threadIdx.x;
    if (t < n4) p[t] = make_float4(0.f, 0.f, 0.f, 0.f);
}
__global__ void relu_kernel(float* p, long long n) {
    long long t = (long long)blockIdx.x * blockDim.x + threadIdx.x;
    if (t < n) p[t] = fmaxf(p[t], 0.f);
}
__global__ void init_bias_kernel(float* C, const float* __restrict__ bias, long long M, int N) {
    long long t = (long long)blockIdx.x * blockDim.x + threadIdx.x;
    if (t < M * N) C[t] = bias[t % N];
}

// ---------------- graph prep: counts -> scan -> scatter (CSR) ----------------
__global__ void count_kernel(const int* __restrict__ eidx, const int* __restrict__ etype) {
    int e = blockIdx.x * blockDim.x + threadIdx.x;
    if (e >= EE_) return;
    atomicAdd(&g_cnt[eidx[EE_ + e] * R_ + etype[e]], 1);
}
__global__ void scan_kernel() {
    __shared__ int part[1024];
    int tid = threadIdx.x;
    int base = tid * 40;
    int s = 0;
#pragma unroll 8
    for (int i = 0; i < 40; ++i) s += g_cnt[base + i];
    part[tid] = s;
    __syncthreads();
    for (int o = 1; o < 1024; o <<= 1) {
        int v = (tid >= o) ? part[tid - o] : 0;
        __syncthreads();
        part[tid] += v;
        __syncthreads();
    }
    int run = tid ? part[tid - 1] : 0;
#pragma unroll 8
    for (int i = 0; i < 40; ++i) {
        int c = g_cnt[base + i];
        g_off[base + i] = run;
        g_cur[base + i] = run;
        run += c;
    }
    if (tid == 1023) g_off[NR_] = run;
}
__global__ void scatter_kernel(const int* __restrict__ eidx, const int* __restrict__ etype) {
    int e = blockIdx.x * blockDim.x + threadIdx.x;
    if (e >= EE_) return;
    int pos = atomicAdd(&g_cur[eidx[EE_ + e] * R_ + etype[e]], 1);
    g_elist[pos] = eidx[e];
}

// x0 fp32 + split(x0); thread owns an n-pair of columns
__global__ void gather_mean_kernel(const float* __restrict__ tok, const int* __restrict__ wti) {
    long long t = (long long)blockIdx.x * blockDim.x + threadIdx.x;
    if (t >= (long long)NN_ * D2_) return;
    int n = (int)(t / D2_);
    int d = (int)(t % D2_) * 2;
    const int* w = wti + n * TPW_;
    float v0 = 0.f, v1 = 0.f;
#pragma unroll
    for (int i = 0; i < TPW_; ++i) {
        const float* r = tok + (size_t)w[i] * D_ + d;
        v0 += r[0]; v1 += r[1];
    }
    v0 *= 0.25f; v1 *= 0.25f;
    *(float2*)(g_x + (size_t)n * D_ + d) = make_float2(v0, v1);
    uint32_t h, l;
    split2(v0, v1, h, l);
    g_xhi[t] = h;
    g_xlo[t] = l;
}

// one CTA per dst node, 192 threads; thread owns 4 feature cols; writes split(h) directly.
__global__ void __launch_bounds__(192)
csr_agg_kernel(const float* __restrict__ x) {
    int dst = blockIdx.x;
    int d = threadIdx.x * 4;
#pragma unroll
    for (int r = 0; r < R_; ++r) {
        int beg = g_off[dst * R_ + r];
        int end = g_off[dst * R_ + r + 1];
        float4 a = make_float4(0.f, 0.f, 0.f, 0.f);
        for (int i = beg; i < end; ++i) {
            int src = g_elist[i];
            float4 v = *(const float4*)(x + (size_t)src * D_ + d);
            a.x += v.x; a.y += v.y; a.z += v.z; a.w += v.w;
        }
        float s = (end > beg) ? (1.f / (float)(end - beg)) : 0.f;
        a.x *= s; a.y *= s; a.z *= s; a.w *= s;
        uint32_t h0, l0, h1, l1;
        split2(a.x, a.y, h0, l0);
        split2(a.z, a.w, h1, l1);
        size_t o = ((size_t)r * NN_ + dst) * D2_ + threadIdx.x * 2;
        *(uint2*)&g_hhi[o] = make_uint2(h0, h1);
        *(uint2*)&g_hlo[o] = make_uint2(l0, l1);
    }
}

// Wcat(3840x768) -> split bf16 [k][n-pair]
__global__ void convertB_kernel(const float* __restrict__ Wrel, const float* __restrict__ Wroot) {
    int t = blockIdx.x * blockDim.x + threadIdx.x;
    if (t >= KTOT_ * D2_) return;
    int k = t / D2_;
    int n = (t - k * D2_) * 2;
    const float* bp = (k < 4 * D_) ? (Wrel + (size_t)k * D_ + n)
                                   : (Wroot + (size_t)(k - 4 * D_) * D_ + n);
    uint32_t h, l;
    split2(bp[0], bp[1], h, l);
    g_whi[t] = h;
    g_wlo[t] = l;
}

// ---------------- split-bf16 tensor GEMM: all cp.async + ldmatrix ----------------
// C(NN_ x 768) = relu( [h0..h3|x](NN_ x 3840) @ Wcat + bias ); optional split(C) out.
#define GBM 128
#define GBN 256
#define GBK 32
#define NSTG (KTOT_ / GBK)   // 120
#define APIT 80              // A row pitch bytes (64 data + 16 pad)
#define BPIT 528             // B row pitch bytes (512 data + 16 pad)
#define ASZB (GBM * APIT)    // 10240 per A half
#define BSZB (GBK * BPIT)    // 16896 per B half
#define SBUFB (2 * ASZB + 2 * BSZB)   // 54272 per stage
#define GSMEM (3 * SBUFB)             // 162816

__global__ void __launch_bounds__(256, 1)
gemm_rgcn(const uint32_t* __restrict__ Hhi, const uint32_t* __restrict__ Hlo,
          const uint32_t* __restrict__ Xhi, const uint32_t* __restrict__ Xlo,
          const uint32_t* __restrict__ Bhi, const uint32_t* __restrict__ Blo,
          const float* __restrict__ bias, float* __restrict__ C,
          uint32_t* __restrict__ Shi, uint32_t* __restrict__ Slo) {
    extern __shared__ char smem[];
    const uint32_t sb = smem_u32(smem);
    const int tid  = threadIdx.x;
    const int wid  = tid >> 5;
    const int lane = tid & 31;
    const int g    = lane >> 2;
    const int tc   = lane & 3;
    const int wm   = wid & 3;        // 0..3 -> 32-row slice
    const int wn   = wid >> 2;       // 0..1 -> 128-col slice
    const int m0   = blockIdx.y * GBM;
    const int n0   = blockIdx.x * GBN;
    const int l15  = lane & 15;
    const int lhi  = (lane >> 4) * 16;

    float acc[2][16][4];
#pragma unroll
    for (int i = 0; i < 2; ++i)
#pragma unroll
        for (int j = 0; j < 16; ++j)
#pragma unroll
            for (int q = 0; q < 4; ++q) acc[i][j][q] = 0.f;

    auto issueA = [&](int kc, int buf) {
        const int k0 = kc * GBK;
        const int r  = k0 / D_;
        const int dq = (k0 - r * D_) >> 1;
        const uint32_t* sH;
        const uint32_t* sL;
        if (r < 4) {
            size_t base = ((size_t)r * NN_ + m0) * D2_ + dq;
            sH = Hhi + base; sL = Hlo + base;
        } else {
            size_t base = (size_t)m0 * D2_ + dq;
            sH = Xhi + base; sL = Xlo + base;
        }
        const uint32_t aB = sb + (uint32_t)buf * SBUFB;
#pragma unroll
        for (int i = 0; i < 2; ++i) {
            int c = tid + i * 256;
            int row = c >> 2, seg = c & 3;
            size_t off = (size_t)row * D2_ + seg * 4;
            uint32_t d = aB + row * APIT + seg * 16;
            cp16(d, sH + off);
            cp16(d + ASZB, sL + off);
        }
    };
    auto issueB = [&](int kc, int buf) {
        const int k0 = kc * GBK;
        const uint32_t* sH = Bhi + (size_t)k0 * D2_ + (n0 >> 1);
        const uint32_t* sL = Blo + (size_t)k0 * D2_ + (n0 >> 1);
        const uint32_t bB = sb + (uint32_t)buf * SBUFB + 2 * ASZB;
#pragma unroll
        for (int i = 0; i < 4; ++i) {
            int c = tid + i * 256;
            int row = c >> 5, seg = c & 31;
            size_t off = (size_t)row * D2_ + seg * 4;
            uint32_t d = bB + row * BPIT + seg * 16;
            cp16(d, sH + off);
            cp16(d + BSZB, sL + off);
        }
    };
    auto compute = [&](uint32_t sbase) {
        const uint32_t aBase = sbase + (wm * 32 + l15) * APIT + lhi;
        const uint32_t bBase = sbase + 2 * ASZB + l15 * BPIT + wn * 256 + lhi;
#pragma unroll
        for (int ks = 0; ks < 2; ++ks) {
            uint32_t aH[2][4], aL[2][4];
#pragma unroll
            for (int mt = 0; mt < 2; ++mt) {
                uint32_t ad = aBase + mt * (16 * APIT) + ks * 32;
                ldmx4(aH[mt], ad);
                ldmx4(aL[mt], ad + ASZB);
            }
#pragma unroll
            for (int p = 0; p < 8; ++p) {
                uint32_t bh[4], bl[4];
                uint32_t bd = bBase + ks * (16 * BPIT) + p * 32;
                ldmx4t(bh, bd);
                ldmx4t(bl, bd + BSZB);
#pragma unroll
                for (int mt = 0; mt < 2; ++mt)
#pragma unroll
                    for (int h2 = 0; h2 < 2; ++h2) {
                        float* a = acc[mt][p * 2 + h2];
                        uint32_t b2h[2] = { bh[h2 * 2], bh[h2 * 2 + 1] };
                        uint32_t b2l[2] = { bl[h2 * 2], bl[h2 * 2 + 1] };
                        mma16816(a, aH[mt], b2h);
                        mma16816(a, aH[mt], b2l);
                        mma16816(a, aL[mt], b2h);
                    }
            }
        }
    };

    issueA(0, 0); issueB(0, 0);
    asm volatile("cp.async.commit_group;" ::: "memory");
    issueA(1, 1); issueB(1, 1);
    asm volatile("cp.async.commit_group;" ::: "memory");

#pragma unroll 1
    for (int kc = 0; kc < NSTG; ++kc) {
        if (kc + 2 < NSTG) {
            int buf = (kc + 2) % 3;
            issueA(kc + 2, buf); issueB(kc + 2, buf);
            asm volatile("cp.async.commit_group;" ::: "memory");
            asm volatile("cp.async.wait_group 2;" ::: "memory");
        } else {
            asm volatile("cp.async.wait_group 0;" ::: "memory");
        }
        __syncthreads();
        compute(sb + (uint32_t)(kc % 3) * SBUFB);
        __syncthreads();
    }

    // ---- epilogue: bias + relu (+ optional split out) ----
#pragma unroll
    for (int mt = 0; mt < 2; ++mt) {
        int row = m0 + wm * 32 + mt * 16 + g;
#pragma unroll
        for (int nt = 0; nt < 16; ++nt) {
            int col = n0 + wn * 128 + nt * 8 + tc * 2;
            float b0 = __ldg(bias + col);
            float b1 = __ldg(bias + col + 1);
            float2 v0 = make_float2(fmaxf(acc[mt][nt][0] + b0, 0.f),
                                    fmaxf(acc[mt][nt][1] + b1, 0.f));
            float2 v1 = make_float2(fmaxf(acc[mt][nt][2] + b0, 0.f),
                                    fmaxf(acc[mt][nt][3] + b1, 0.f));
            *(float2*)(C + (size_t)row * D_ + col)       = v0;
            *(float2*)(C + (size_t)(row + 8) * D_ + col) = v1;
            if (Shi) {
                uint32_t h, l;
                split2(v0.x, v0.y, h, l);
                Shi[(size_t)row * D2_ + (col >> 1)] = h;
                Slo[(size_t)row * D2_ + (col >> 1)] = l;
                split2(v1.x, v1.y, h, l);
                Shi[(size_t)(row + 8) * D2_ + (col >> 1)] = h;
                Slo[(size_t)(row + 8) * D2_ + (col >> 1)] = l;
            }
        }
    }
}

// ---------------- fp32 SGEMM for small head GEMMs ----------------
#define BM 128
#define BN 128
#define BK 8
#define TM 8
#define TN 8
__global__ __launch_bounds__(256)
void sgemm_acc(const float* __restrict__ A, const float* __restrict__ Bm,
               float* __restrict__ C, int M, int N, int K) {
    const int brow = blockIdx.y, bcol = blockIdx.x;
    const int tid = threadIdx.x;
    __shared__ float As[BK][BM];
    __shared__ float Bs[BK][BN];
    const int threadRow = tid / (BN / TN);
    const int threadCol = tid % (BN / TN);
    const int aRow = tid >> 1;
    const int aCol = (tid & 1) * 4;
    const int bRow = tid >> 5;
    const int bCol = (tid & 31) * 4;
    float acc[TM][TN] = {};
    float regM[TM], regN[TN];
    const int gARow = brow * BM + aRow;
    const bool aValid = (gARow < M);
    const float* Aptr = A + (size_t)gARow * K;
    const float* Bptr = Bm + bcol * BN;
    for (int k0 = 0; k0 < K; k0 += BK) {
        float4 av = aValid ? *(const float4*)(Aptr + k0 + aCol) : make_float4(0.f, 0.f, 0.f, 0.f);
        As[aCol + 0][aRow] = av.x;
        As[aCol + 1][aRow] = av.y;
        As[aCol + 2][aRow] = av.z;
        As[aCol + 3][aRow] = av.w;
        *(float4*)&Bs[bRow][bCol] = *(const float4*)(Bptr + (size_t)(k0 + bRow) * N + bCol);
        __syncthreads();
#pragma unroll
        for (int k = 0; k < BK; ++k) {
#pragma unroll
            for (int i = 0; i < TM; ++i) regM[i] = As[k][threadRow * TM + i];
#pragma unroll
            for (int j = 0; j < TN; ++j) regN[j] = Bs[k][threadCol * TN + j];
#pragma unroll
            for (int i = 0; i < TM; ++i)
#pragma unroll
                for (int j = 0; j < TN; ++j)
                    acc[i][j] += regM[i] * regN[j];
        }
        __syncthreads();
    }
#pragma unroll
    for (int i = 0; i < TM; ++i) {
        int r = brow * BM + threadRow * TM + i;
        if (r < M) {
            float* Cp = C + (size_t)r * N + bcol * BN + threadCol * TN;
#pragma unroll
            for (int j = 0; j < TN; j += 4) {
                float4 cv = *(float4*)(Cp + j);
                cv.x += acc[i][j + 0];
                cv.y += acc[i][j + 1];
                cv.z += acc[i][j + 2];
                cv.w += acc[i][j + 3];
                *(float4*)(Cp + j) = cv;
            }
        }
    }
}

// ---------------- head kernels ----------------
__global__ void ev_pool_kernel() {
    int t = blockIdx.x * blockDim.x + threadIdx.x;
    if (t >= SEQS_ * DOUT_) return;
    int s = t / DOUT_, d = t % DOUT_;
    const float* base = g_x + (size_t)s * WORDS_ * DOUT_ + d;
    float sum = 0.f, mx = -1e30f;
#pragma unroll 8
    for (int w = 0; w < WORDS_; ++w) {
        float v = base[(size_t)w * DOUT_];
        sum += v;
        mx = fmaxf(mx, v);
    }
    g_ev[s * (2 * DOUT_) + d]         = sum * (1.f / WORDS_);
    g_ev[s * (2 * DOUT_) + DOUT_ + d] = mx;
}
__global__ void build_attin_kernel(const float* __restrict__ tok, const int* __restrict__ csi) {
    int t = blockIdx.x * blockDim.x + threadIdx.x;
    const int W = D_ + 2 * DOUT_;
    if (t >= SEQS_ * W) return;
    int s = t / W, c = t % W;
    if (c < D_) {
        int seq = csi[s / EVI_];
        g_attin[t] = tok[(size_t)seq * L_ * D_ + c];
    } else {
        g_attin[t] = g_ev[s * (2 * DOUT_) + (c - D_)];
    }
}
__global__ void dotp_kernel(const float* __restrict__ att_w1) {
    int s = blockIdx.x;
    int tid = threadIdx.x;
    float acc = 0.f;
    for (int k = tid; k < DOUT_; k += 256)
        acc += g_hatt[(size_t)s * DOUT_ + k] * att_w1[k];
#pragma unroll
    for (int o = 16; o; o >>= 1) acc += __shfl_down_sync(0xffffffffu, acc, o);
    __shared__ float sw[8];
    if ((tid & 31) == 0) sw[tid >> 5] = acc;
    __syncthreads();
    if (tid == 0) {
        float r = 0.f;
#pragma unroll
        for (int w = 0; w < 8; ++w) r += sw[w];
        g_p[s] = r;
    }
}
__global__ void softmax_att_kernel(float* __restrict__ out) {
    int b = blockIdx.x;
    if (threadIdx.x != 0) return;
    float pv[EVI_];
    float m = -1e30f;
#pragma unroll
    for (int e = 0; e < EVI_; ++e) { pv[e] = g_p[b * EVI_ + e]; m = fmaxf(m, pv[e]); }
    float s = 0.f;
#pragma unroll
    for (int e = 0; e < EVI_; ++e) { pv[e] = expf(pv[e] - m); s += pv[e]; }
    float is = 1.f / s;
#pragma unroll
    for (int e = 0; e < EVI_; ++e) {
        g_a[b * EVI_ + e] = pv[e] * is;
        float p = g_p[b * EVI_ + e];
        out[B_ * NC_ + b * EVI_ + e] = 1.f / (1.f + expf(-p));
    }
}
__global__ void graph_rep_kernel(const float* __restrict__ concat_cls) {
    int t = blockIdx.x * blockDim.x + threadIdx.x;
    const int W = 2 * DOUT_ + D_;
    if (t >= B_ * W) return;
    int b = t / W, c = t % W;
    if (c < 2 * DOUT_) {
        float acc = 0.f;
#pragma unroll
        for (int e = 0; e < EVI_; ++e)
            acc += g_a[b * EVI_ + e] * g_ev[(size_t)(b * EVI_ + e) * (2 * DOUT_) + c];
        g_rep[t] = acc;
    } else {
        g_rep[t] = concat_cls[b * D_ + (c - 2 * DOUT_)];
    }
}
__global__ void final_kernel(const float* __restrict__ lin2_w,
                             const float* __restrict__ lin2_b,
                             float* __restrict__ out) {
    int b = blockIdx.x;
    int tid = threadIdx.x;
    float a0 = 0.f, a1 = 0.f, a2 = 0.f;
    for (int k = tid; k < LH_; k += 128) {
        float h = g_hid[(size_t)b * LH_ + k];
        a0 += h * lin2_w[k * NC_ + 0];
        a1 += h * lin2_w[k * NC_ + 1];
        a2 += h * lin2_w[k * NC_ + 2];
    }
#pragma unroll
    for (int o = 16; o; o >>= 1) {
        a0 += __shfl_down_sync(0xffffffffu, a0, o);
        a1 += __shfl_down_sync(0xffffffffu, a1, o);
        a2 += __shfl_down_sync(0xffffffffu, a2, o);
    }
    __shared__ float s0[4], s1[4], s2[4];
    if ((tid & 31) == 0) { int w = tid >> 5; s0[w] = a0; s1[w] = a1; s2[w] = a2; }
    __syncthreads();
    if (tid == 0) {
        float l0 = s0[0] + s0[1] + s0[2] + s0[3] + lin2_b[0];
        float l1 = s1[0] + s1[1] + s1[2] + s1[3] + lin2_b[1];
        float l2 = s2[0] + s2[1] + s2[2] + s2[3] + lin2_b[2];
        float m = fmaxf(l0, fmaxf(l1, l2));
        float lse = logf(expf(l0 - m) + expf(l1 - m) + expf(l2 - m)) + m;
        out[b * NC_ + 0] = l0 - lse;
        out[b * NC_ + 1] = l1 - lse;
        out[b * NC_ + 2] = l2 - lse;
    }
}

// ---------------- launch ----------------
static inline dim3 gemm_grid_f32(int M, int N) {
    return dim3((N + BN - 1) / BN, (M + BM - 1) / BM);
}

extern "C" void kernel_launch(void* const* d_in, const int* in_sizes, int n_in,
                              void* d_out, int out_size) {
    const float* token_feats = (const float*)d_in[0];
    const float* concat_cls  = (const float*)d_in[1];
    const float* W_rel1      = (const float*)d_in[2];
    const float* W_root1     = (const float*)d_in[3];
    const float* b1          = (const float*)d_in[4];
    const float* W_rel2      = (const float*)d_in[5];
    const float* W_root2     = (const float*)d_in[6];
    const float* b2          = (const float*)d_in[7];
    const float* att_w0      = (const float*)d_in[8];
    const float* att_w1      = (const float*)d_in[9];
    const float* lin1_w      = (const float*)d_in[10];
    const float* lin1_b      = (const float*)d_in[11];
    const float* lin2_w      = (const float*)d_in[12];
    const float* lin2_b      = (const float*)d_in[13];
    const int*   wti         = (const int*)d_in[14];
    const int*   eidx        = (const int*)d_in[15];
    const int*   etype       = (const int*)d_in[16];
    const int*   csi         = (const int*)d_in[17];
    float* out = (float*)d_out;

    float *p_x, *p_acc, *p_attin, *p_hatt, *p_rep, *p_hid;
    int* p_cnt;
    uint32_t *p_hhi, *p_hlo, *p_xhi, *p_xlo, *p_yhi, *p_ylo, *p_whi, *p_wlo;
    cudaGetSymbolAddress((void**)&p_x,     g_x);
    cudaGetSymbolAddress((void**)&p_acc,   g_acc);
    cudaGetSymbolAddress((void**)&p_cnt,   g_cnt);
    cudaGetSymbolAddress((void**)&p_attin, g_attin);
    cudaGetSymbolAddress((void**)&p_hatt,  g_hatt);
    cudaGetSymbolAddress((void**)&p_rep,   g_rep);
    cudaGetSymbolAddress((void**)&p_hid,   g_hid);
    cudaGetSymbolAddress((void**)&p_hhi,   g_hhi);
    cudaGetSymbolAddress((void**)&p_hlo,   g_hlo);
    cudaGetSymbolAddress((void**)&p_xhi,   g_xhi);
    cudaGetSymbolAddress((void**)&p_xlo,   g_xlo);
    cudaGetSymbolAddress((void**)&p_yhi,   g_yhi);
    cudaGetSymbolAddress((void**)&p_ylo,   g_ylo);
    cudaGetSymbolAddress((void**)&p_whi,   g_whi);
    cudaGetSymbolAddress((void**)&p_wlo,   g_wlo);

    cudaFuncSetAttribute(gemm_rgcn, cudaFuncAttributeMaxDynamicSharedMemorySize, GSMEM);

    const int T = 256;
    const long long NQ = (long long)NN_ * D2_;
    const int CVB = KTOT_ * D2_;
    const dim3 ggrid(D_ / GBN, NN_ / GBM);   // (3, 80)

    // --- graph prep: CSR ---
    zero4_kernel<<<(NR_ / 4 + T - 1) / T, T>>>((float4*)p_cnt, NR_ / 4);
    count_kernel<<<(EE_ + T - 1) / T, T>>>(eidx, etype);
    scan_kernel<<<1, 1024>>>();
    scatter_kernel<<<(EE_ + T - 1) / T, T>>>(eidx, etype);

    // --- x0 (fp32 + split) ---
    gather_mean_kernel<<<(unsigned)((NQ + T - 1) / T), T>>>(token_feats, wti);

    // --- layer 1 ---
    csr_agg_kernel<<<NN_, 192>>>(p_x);
    convertB_kernel<<<(CVB + T - 1) / T, T>>>(W_rel1, W_root1);
    gemm_rgcn<<<ggrid, 256, GSMEM>>>(p_hhi, p_hlo, p_xhi, p_xlo, p_whi, p_wlo,
                                     b1, p_acc, p_yhi, p_ylo);

    // --- layer 2 ---
    csr_agg_kernel<<<NN_, 192>>>(p_acc);
    convertB_kernel<<<(CVB + T - 1) / T, T>>>(W_rel2, W_root2);
    gemm_rgcn<<<ggrid, 256, GSMEM>>>(p_hhi, p_hlo, p_yhi, p_ylo, p_whi, p_wlo,
                                     b2, p_x, nullptr, nullptr);

    // --- evidence pooling + attention ---
    ev_pool_kernel<<<(SEQS_ * DOUT_ + T - 1) / T, T>>>();
    build_attin_kernel<<<(SEQS_ * (D_ + 2 * DOUT_) + T - 1) / T, T>>>(token_feats, csi);
    zero4_kernel<<<(SEQS_ * DOUT_ / 4 + T - 1) / T, T>>>((float4*)p_hatt, SEQS_ * DOUT_ / 4);
    sgemm_acc<<<gemm_grid_f32(SEQS_, DOUT_), 256>>>(p_attin, att_w0, p_hatt,
                                                    SEQS_, DOUT_, D_ + 2 * DOUT_);
    relu_kernel<<<(SEQS_ * DOUT_ + T - 1) / T, T>>>(p_hatt, (long long)SEQS_ * DOUT_);
    dotp_kernel<<<SEQS_, 256>>>(att_w1);
    softmax_att_kernel<<<B_, 32>>>(out);

    // --- graph readout + classifier ---
    graph_rep_kernel<<<(B_ * (2 * DOUT_ + D_) + T - 1) / T, T>>>(concat_cls);
    init_bias_kernel<<<(B_ * LH_ + T - 1) / T, T>>>(p_hid, lin1_b, B_, LH_);
    sgemm_acc<<<gemm_grid_f32(B_, LH_), 256>>>(p_rep, lin1_w, p_hid, B_, LH_, 2 * DOUT_ + D_);
    relu_kernel<<<(B_ * LH_ + T - 1) / T, T>>>(p_hid, (long long)B_ * LH_);
    final_kernel<<<B_, 128>>>(lin2_w, lin2_b, out);
}

// round 8
// speedup vs baseline: 1.1804x; 1.1804x over previous
#include <cuda_runtime.h>
#include <cuda_fp16.h>
#include <math.h>
#include <stdint.h>

// ---------------- problem constants ----------------
#define B_      64
#define EVI_    5
#define SEQS_   (B_ * EVI_)          // 320
#define L_      256
#define D_      768
#define WORDS_  32
#define TPW_    4
#define NN_     (SEQS_ * WORDS_)     // 10240 nodes
#define EE_     (NN_ * 16)           // 163840 edges
#define R_      4
#define DOUT_   768
#define LH_     1024
#define NC_     3
#define KTOT_   (5 * D_)             // 3840 fused K
#define NR_     (NN_ * R_)           // 40960 segments
#define KP2_    (KTOT_ / 2)          // 1920 k-pairs

// ---------------- scratch (device globals; no allocs allowed) ----------------
__device__ float    g_x   [(size_t)NN_ * D_];        // x0 / x2
__device__ float    g_acc [(size_t)NN_ * D_];        // x1
__device__ float    g_h   [(size_t)R_ * NN_ * D_];   // per-relation aggregation
__device__ uint32_t g_bhi [(size_t)KP2_ * D_];       // B hi (fp16 k-pair packed) [k2][n]
__device__ uint32_t g_blo [(size_t)KP2_ * D_];       // B lo
__device__ int      g_cnt [NR_];
__device__ int      g_off [NR_ + 1];
__device__ int      g_cur [NR_];
__device__ int      g_elist[EE_];
__device__ float    g_ev  [SEQS_ * 2 * DOUT_];
__device__ float    g_attin[SEQS_ * (D_ + 2 * DOUT_)];
__device__ float    g_hatt[SEQS_ * DOUT_];
__device__ float    g_p   [SEQS_];
__device__ float    g_a   [SEQS_];
__device__ float    g_rep [B_ * (2 * DOUT_ + D_)];
__device__ float    g_hid [B_ * LH_];

// ---------------- small device helpers ----------------
__device__ __forceinline__ uint32_t smem_u32(const void* p) {
    uint32_t a;
    asm("{ .reg .u64 t; cvta.to.shared.u64 t, %1; cvt.u32.u64 %0, t; }" : "=r"(a) : "l"(p));
    return a;
}
// pack {v0 -> low16, v1 -> high16} as fp16x2
__device__ __forceinline__ uint32_t packh2(float v0, float v1) {
    __half h0 = __float2half_rn(v0);
    __half h1 = __float2half_rn(v1);
    return ((uint32_t)__half_as_ushort(h1) << 16) | (uint32_t)__half_as_ushort(h0);
}
__device__ __forceinline__ void splith2(float v0, float v1, uint32_t& h, uint32_t& l) {
    __half h0 = __float2half_rn(v0);
    __half h1 = __float2half_rn(v1);
    h = ((uint32_t)__half_as_ushort(h1) << 16) | (uint32_t)__half_as_ushort(h0);
    l = packh2(v0 - __half2float(h0), v1 - __half2float(h1));
}
__device__ __forceinline__ void mma16816h(float* c, const uint32_t* a, const uint32_t* b) {
    asm volatile("mma.sync.aligned.m16n8k16.row.col.f32.f16.f16.f32 "
                 "{%0,%1,%2,%3}, {%4,%5,%6,%7}, {%8,%9}, {%0,%1,%2,%3};"
                 : "+f"(c[0]), "+f"(c[1]), "+f"(c[2]), "+f"(c[3])
                 : "r"(a[0]), "r"(a[1]), "r"(a[2]), "r"(a[3]), "r"(b[0]), "r"(b[1]));
}
__device__ __forceinline__ void cp16(uint32_t dst, const void* src) {
    asm volatile("cp.async.cg.shared.global [%0], [%1], 16;" :: "r"(dst), "l"(src));
}

// ---------------- utility kernels ----------------
__global__ void zero4_kernel(float4* p, long long n4) {
    long long t = (long long)blockIdx.x * blockDim.x + threadIdx.x;
    if (t < n4) p[t] = make_float4(0.f, 0.f, 0.f, 0.f);
}
__global__ void relu_kernel(float* p, long long n) {
    long long t = (long long)blockIdx.x * blockDim.x + threadIdx.x;
    if (t < n) p[t] = fmaxf(p[t], 0.f);
}
__global__ void init_bias_kernel(float* C, const float* __restrict__ bias, long long M, int N) {
    long long t = (long long)blockIdx.x * blockDim.x + threadIdx.x;
    if (t < M * N) C[t] = bias[t % N];
}

// ---------------- graph prep: counts -> scan -> scatter (CSR) ----------------
__global__ void count_kernel(const int* __restrict__ eidx, const int* __restrict__ etype) {
    int e = blockIdx.x * blockDim.x + threadIdx.x;
    if (e >= EE_) return;
    atomicAdd(&g_cnt[eidx[EE_ + e] * R_ + etype[e]], 1);
}
__global__ void scan_kernel() {
    __shared__ int part[1024];
    int tid = threadIdx.x;
    int base = tid * 40;
    int s = 0;
#pragma unroll 8
    for (int i = 0; i < 40; ++i) s += g_cnt[base + i];
    part[tid] = s;
    __syncthreads();
    for (int o = 1; o < 1024; o <<= 1) {
        int v = (tid >= o) ? part[tid - o] : 0;
        __syncthreads();
        part[tid] += v;
        __syncthreads();
    }
    int run = tid ? part[tid - 1] : 0;
#pragma unroll 8
    for (int i = 0; i < 40; ++i) {
        int c = g_cnt[base + i];
        g_off[base + i] = run;
        g_cur[base + i] = run;
        run += c;
    }
    if (tid == 1023) g_off[NR_] = run;
}
__global__ void scatter_kernel(const int* __restrict__ eidx, const int* __restrict__ etype) {
    int e = blockIdx.x * blockDim.x + threadIdx.x;
    if (e >= EE_) return;
    int pos = atomicAdd(&g_cur[eidx[EE_ + e] * R_ + etype[e]], 1);
    g_elist[pos] = eidx[e];
}

__global__ void gather_mean_kernel(const float* __restrict__ tok, const int* __restrict__ wti) {
    long long t = (long long)blockIdx.x * blockDim.x + threadIdx.x;
    if (t >= (long long)NN_ * D_) return;
    int n = (int)(t / D_);
    int d = (int)(t % D_);
    const int* w = wti + n * TPW_;
    float s = tok[(size_t)w[0] * D_ + d] + tok[(size_t)w[1] * D_ + d]
            + tok[(size_t)w[2] * D_ + d] + tok[(size_t)w[3] * D_ + d];
    g_x[t] = 0.25f * s;
}

// one CTA per dst node, 192 threads; thread owns 4 feature columns.
__global__ void __launch_bounds__(192)
csr_agg_kernel(const float* __restrict__ x) {
    int dst = blockIdx.x;
    int d = threadIdx.x * 4;
#pragma unroll
    for (int r = 0; r < R_; ++r) {
        int beg = g_off[dst * R_ + r];
        int end = g_off[dst * R_ + r + 1];
        float4 a = make_float4(0.f, 0.f, 0.f, 0.f);
        for (int i = beg; i < end; ++i) {
            int src = g_elist[i];
            float4 v = *(const float4*)(x + (size_t)src * D_ + d);
            a.x += v.x; a.y += v.y; a.z += v.z; a.w += v.w;
        }
        float s = (end > beg) ? (1.f / (float)(end - beg)) : 0.f;
        a.x *= s; a.y *= s; a.z *= s; a.w *= s;
        *(float4*)(g_h + ((size_t)r * NN_ + dst) * D_ + d) = a;
    }
}

// ---------------- B pre-pack: Wcat(3840x768) -> k-pair packed split fp16 ----------------
__global__ void convertB_kernel(const float* __restrict__ Wrel, const float* __restrict__ Wroot) {
    int t = blockIdx.x * blockDim.x + threadIdx.x;
    if (t >= KP2_ * D_) return;
    int k2 = t / D_;
    int n  = t - k2 * D_;
    int k  = 2 * k2;
    const float* bp = (k < 4 * D_) ? (Wrel + (size_t)k * D_ + n)
                                   : (Wroot + (size_t)(k - 4 * D_) * D_ + n);
    uint32_t h, l;
    splith2(bp[0], bp[D_], h, l);
    g_bhi[t] = h;
    g_blo[t] = l;
}

// ---------------- fp16 2-pass tensor GEMM: A reg-staged (single fp16), B split cp.async ----------------
// C(NN_ x 768) = relu( [h0|h1|h2|h3|x](NN_ x 3840) @ Wcat + bias )
#define GBM 128
#define GBN 256
#define GBK 32
#define NSTG (KTOT_ / GBK)   // 120
#define AP_  20              // A smem pitch u32 (16 k-pairs + 4 pad)
#define BP_  264             // B smem pitch u32 (256 + 8 pad)
#define ASZ_ (GBM * AP_)     // 2560 u32
#define BSZ_ (16 * BP_)      // 4224 u32
#define SBUF (ASZ_ + 2 * BSZ_)       // 11008 u32 per stage
#define GSMEM (2 * SBUF * 4)         // 88064 bytes

__global__ void __launch_bounds__(256, 1)
gemm_rgcn(const float* __restrict__ gh, const float* __restrict__ xroot,
          const uint32_t* __restrict__ Bhi, const uint32_t* __restrict__ Blo,
          const float* __restrict__ bias, float* __restrict__ C) {
    extern __shared__ uint32_t sm[];
    const uint32_t sb = smem_u32(sm);
    const int tid  = threadIdx.x;
    const int wid  = tid >> 5;
    const int lane = tid & 31;
    const int g    = lane >> 2;
    const int tc   = lane & 3;
    const int wm   = wid & 3;        // 0..3 -> 32-row slice
    const int wn   = wid >> 2;       // 0..1 -> 128-col slice
    const int m0   = blockIdx.y * GBM;
    const int n0   = blockIdx.x * GBN;

    float acc[2][16][4];
#pragma unroll
    for (int i = 0; i < 2; ++i)
#pragma unroll
        for (int j = 0; j < 16; ++j)
#pragma unroll
            for (int q = 0; q < 4; ++q) acc[i][j][q] = 0.f;

    float4 pa[4];

    auto prefetchA = [&](int kc) {
        const int k0 = kc * GBK;
        const int r  = k0 / D_;
        const int d0 = k0 - r * D_;
        const float* Ab = (r < 4) ? (gh + ((size_t)r * NN_ + m0) * D_ + d0)
                                  : (xroot + (size_t)m0 * D_ + d0);
#pragma unroll
        for (int i = 0; i < 4; ++i) {
            int c = tid + i * 256;
            int m = c >> 3, kq = c & 7;
            pa[i] = *(const float4*)(Ab + (size_t)m * D_ + kq * 4);
        }
    };
    auto storeA = [&](uint32_t* buf) {
#pragma unroll
        for (int i = 0; i < 4; ++i) {
            int c = tid + i * 256;
            int m = c >> 3, kq = c & 7;
            float4 v = pa[i];
            uint32_t h0 = packh2(v.x, v.y);
            uint32_t h1 = packh2(v.z, v.w);
            *(uint2*)&buf[m * AP_ + kq * 2] = make_uint2(h0, h1);
        }
    };
    auto issueB = [&](int kc, int buf) {
        const int kp0 = kc * 16;
        const uint32_t bbH = sb + (uint32_t)buf * (SBUF * 4) + ASZ_ * 4;
        const uint32_t bbL = bbH + BSZ_ * 4;
#pragma unroll
        for (int i = 0; i < 4; ++i) {
            int c = tid + i * 256;
            int row = c >> 6, seg = c & 63;
            size_t gidx = (size_t)(kp0 + row) * D_ + n0 + seg * 4;
            uint32_t doff = row * (BP_ * 4) + seg * 16;
            cp16(bbH + doff, Bhi + gidx);
            cp16(bbL + doff, Blo + gidx);
        }
    };
    auto compute = [&](const uint32_t* s) {
        const uint32_t* AsH = s;
        const uint32_t* BsH = s + ASZ_;
        const uint32_t* BsL = s + ASZ_ + BSZ_;
#pragma unroll
        for (int ks = 0; ks < 2; ++ks) {
            const int kb = ks * 8;
            uint32_t aH[2][4];
#pragma unroll
            for (int mt = 0; mt < 2; ++mt) {
                int i0 = (wm * 32 + mt * 16 + g) * AP_ + kb + tc;
                int i1 = i0 + 8 * AP_;
                aH[mt][0] = AsH[i0]; aH[mt][1] = AsH[i1];
                aH[mt][2] = AsH[i0 + 4]; aH[mt][3] = AsH[i1 + 4];
            }
#pragma unroll
            for (int ng = 0; ng < 4; ++ng) {
                uint32_t bh[4][2], bl[4][2];
#pragma unroll
                for (int q = 0; q < 4; ++q) {
                    int cb = wn * 128 + (ng * 4 + q) * 8;
                    int j0 = (kb + tc) * BP_ + cb + g;
                    int j1 = j0 + 4 * BP_;
                    bh[q][0] = BsH[j0]; bh[q][1] = BsH[j1];
                    bl[q][0] = BsL[j0]; bl[q][1] = BsL[j1];
                }
#pragma unroll
                for (int mt = 0; mt < 2; ++mt)
#pragma unroll
                    for (int q = 0; q < 4; ++q) {
                        float* a = acc[mt][ng * 4 + q];
                        mma16816h(a, aH[mt], bh[q]);
                        mma16816h(a, aH[mt], bl[q]);
                    }
            }
        }
    };

    // ---- pipeline: A reg double-buffer, B cp.async double-buffer ----
    prefetchA(0);
    storeA(sm);
    issueB(0, 0);
    asm volatile("cp.async.commit_group;" ::: "memory");

#pragma unroll 1
    for (int kc = 0; kc < NSTG; ++kc) {
        const int cur = kc & 1;
        if (kc + 1 < NSTG) {
            issueB(kc + 1, 1 - cur);
            asm volatile("cp.async.commit_group;" ::: "memory");
            prefetchA(kc + 1);
            asm volatile("cp.async.wait_group 1;" ::: "memory");
        } else {
            asm volatile("cp.async.wait_group 0;" ::: "memory");
        }
        __syncthreads();
        compute(sm + cur * SBUF);
        if (kc + 1 < NSTG) storeA(sm + (1 - cur) * SBUF);
        __syncthreads();
    }

    // ---- epilogue: bias + relu ----
#pragma unroll
    for (int mt = 0; mt < 2; ++mt) {
        int row = m0 + wm * 32 + mt * 16 + g;
#pragma unroll
        for (int nt = 0; nt < 16; ++nt) {
            int col = n0 + wn * 128 + nt * 8 + tc * 2;
            float b0 = __ldg(bias + col);
            float b1 = __ldg(bias + col + 1);
            float2 v0 = make_float2(fmaxf(acc[mt][nt][0] + b0, 0.f),
                                    fmaxf(acc[mt][nt][1] + b1, 0.f));
            float2 v1 = make_float2(fmaxf(acc[mt][nt][2] + b0, 0.f),
                                    fmaxf(acc[mt][nt][3] + b1, 0.f));
            *(float2*)(C + (size_t)row * D_ + col)       = v0;
            *(float2*)(C + (size_t)(row + 8) * D_ + col) = v1;
        }
    }
}

// ---------------- fp32 SGEMM for small head GEMMs ----------------
#define BM 128
#define BN 128
#define BK 8
#define TM 8
#define TN 8
__global__ __launch_bounds__(256)
void sgemm_acc(const float* __restrict__ A, const float* __restrict__ Bm,
               float* __restrict__ C, int M, int N, int K) {
    const int brow = blockIdx.y, bcol = blockIdx.x;
    const int tid = threadIdx.x;
    __shared__ float As[BK][BM];
    __shared__ float Bs[BK][BN];
    const int threadRow = tid / (BN / TN);
    const int threadCol = tid % (BN / TN);
    const int aRow = tid >> 1;
    const int aCol = (tid & 1) * 4;
    const int bRow = tid >> 5;
    const int bCol = (tid & 31) * 4;
    float acc[TM][TN] = {};
    float regM[TM], regN[TN];
    const int gARow = brow * BM + aRow;
    const bool aValid = (gARow < M);
    const float* Aptr = A + (size_t)gARow * K;
    const float* Bptr = Bm + bcol * BN;
    for (int k0 = 0; k0 < K; k0 += BK) {
        float4 av = aValid ? *(const float4*)(Aptr + k0 + aCol) : make_float4(0.f, 0.f, 0.f, 0.f);
        As[aCol + 0][aRow] = av.x;
        As[aCol + 1][aRow] = av.y;
        As[aCol + 2][aRow] = av.z;
        As[aCol + 3][aRow] = av.w;
        *(float4*)&Bs[bRow][bCol] = *(const float4*)(Bptr + (size_t)(k0 + bRow) * N + bCol);
        __syncthreads();
#pragma unroll
        for (int k = 0; k < BK; ++k) {
#pragma unroll
            for (int i = 0; i < TM; ++i) regM[i] = As[k][threadRow * TM + i];
#pragma unroll
            for (int j = 0; j < TN; ++j) regN[j] = Bs[k][threadCol * TN + j];
#pragma unroll
            for (int i = 0; i < TM; ++i)
#pragma unroll
                for (int j = 0; j < TN; ++j)
                    acc[i][j] += regM[i] * regN[j];
        }
        __syncthreads();
    }
#pragma unroll
    for (int i = 0; i < TM; ++i) {
        int r = brow * BM + threadRow * TM + i;
        if (r < M) {
            float* Cp = C + (size_t)r * N + bcol * BN + threadCol * TN;
#pragma unroll
            for (int j = 0; j < TN; j += 4) {
                float4 cv = *(float4*)(Cp + j);
                cv.x += acc[i][j + 0];
                cv.y += acc[i][j + 1];
                cv.z += acc[i][j + 2];
                cv.w += acc[i][j + 3];
                *(float4*)(Cp + j) = cv;
            }
        }
    }
}

// ---------------- head kernels ----------------
__global__ void ev_pool_kernel() {
    int t = blockIdx.x * blockDim.x + threadIdx.x;
    if (t >= SEQS_ * DOUT_) return;
    int s = t / DOUT_, d = t % DOUT_;
    const float* base = g_x + (size_t)s * WORDS_ * DOUT_ + d;
    float sum = 0.f, mx = -1e30f;
#pragma unroll 8
    for (int w = 0; w < WORDS_; ++w) {
        float v = base[(size_t)w * DOUT_];
        sum += v;
        mx = fmaxf(mx, v);
    }
    g_ev[s * (2 * DOUT_) + d]         = sum * (1.f / WORDS_);
    g_ev[s * (2 * DOUT_) + DOUT_ + d] = mx;
}
__global__ void build_attin_kernel(const float* __restrict__ tok, const int* __restrict__ csi) {
    int t = blockIdx.x * blockDim.x + threadIdx.x;
    const int W = D_ + 2 * DOUT_;
    if (t >= SEQS_ * W) return;
    int s = t / W, c = t % W;
    if (c < D_) {
        int seq = csi[s / EVI_];
        g_attin[t] = tok[(size_t)seq * L_ * D_ + c];
    } else {
        g_attin[t] = g_ev[s * (2 * DOUT_) + (c - D_)];
    }
}
__global__ void dotp_kernel(const float* __restrict__ att_w1) {
    int s = blockIdx.x;
    int tid = threadIdx.x;
    float acc = 0.f;
    for (int k = tid; k < DOUT_; k += 256)
        acc += g_hatt[(size_t)s * DOUT_ + k] * att_w1[k];
#pragma unroll
    for (int o = 16; o; o >>= 1) acc += __shfl_down_sync(0xffffffffu, acc, o);
    __shared__ float sw[8];
    if ((tid & 31) == 0) sw[tid >> 5] = acc;
    __syncthreads();
    if (tid == 0) {
        float r = 0.f;
#pragma unroll
        for (int w = 0; w < 8; ++w) r += sw[w];
        g_p[s] = r;
    }
}
__global__ void softmax_att_kernel(float* __restrict__ out) {
    int b = blockIdx.x;
    if (threadIdx.x != 0) return;
    float pv[EVI_];
    float m = -1e30f;
#pragma unroll
    for (int e = 0; e < EVI_; ++e) { pv[e] = g_p[b * EVI_ + e]; m = fmaxf(m, pv[e]); }
    float s = 0.f;
#pragma unroll
    for (int e = 0; e < EVI_; ++e) { pv[e] = expf(pv[e] - m); s += pv[e]; }
    float is = 1.f / s;
#pragma unroll
    for (int e = 0; e < EVI_; ++e) {
        g_a[b * EVI_ + e] = pv[e] * is;
        float p = g_p[b * EVI_ + e];
        out[B_ * NC_ + b * EVI_ + e] = 1.f / (1.f + expf(-p));
    }
}
__global__ void graph_rep_kernel(const float* __restrict__ concat_cls) {
    int t = blockIdx.x * blockDim.x + threadIdx.x;
    const int W = 2 * DOUT_ + D_;
    if (t >= B_ * W) return;
    int b = t / W, c = t % W;
    if (c < 2 * DOUT_) {
        float acc = 0.f;
#pragma unroll
        for (int e = 0; e < EVI_; ++e)
            acc += g_a[b * EVI_ + e] * g_ev[(size_t)(b * EVI_ + e) * (2 * DOUT_) + c];
        g_rep[t] = acc;
    } else {
        g_rep[t] = concat_cls[b * D_ + (c - 2 * DOUT_)];
    }
}
__global__ void final_kernel(const float* __restrict__ lin2_w,
                             const float* __restrict__ lin2_b,
                             float* __restrict__ out) {
    int b = blockIdx.x;
    int tid = threadIdx.x;
    float a0 = 0.f, a1 = 0.f, a2 = 0.f;
    for (int k = tid; k < LH_; k += 128) {
        float h = g_hid[(size_t)b * LH_ + k];
        a0 += h * lin2_w[k * NC_ + 0];
        a1 += h * lin2_w[k * NC_ + 1];
        a2 += h * lin2_w[k * NC_ + 2];
    }
#pragma unroll
    for (int o = 16; o; o >>= 1) {
        a0 += __shfl_down_sync(0xffffffffu, a0, o);
        a1 += __shfl_down_sync(0xffffffffu, a1, o);
        a2 += __shfl_down_sync(0xffffffffu, a2, o);
    }
    __shared__ float s0[4], s1[4], s2[4];
    if ((tid & 31) == 0) { int w = tid >> 5; s0[w] = a0; s1[w] = a1; s2[w] = a2; }
    __syncthreads();
    if (tid == 0) {
        float l0 = s0[0] + s0[1] + s0[2] + s0[3] + lin2_b[0];
        float l1 = s1[0] + s1[1] + s1[2] + s1[3] + lin2_b[1];
        float l2 = s2[0] + s2[1] + s2[2] + s2[3] + lin2_b[2];
        float m = fmaxf(l0, fmaxf(l1, l2));
        float lse = logf(expf(l0 - m) + expf(l1 - m) + expf(l2 - m)) + m;
        out[b * NC_ + 0] = l0 - lse;
        out[b * NC_ + 1] = l1 - lse;
        out[b * NC_ + 2] = l2 - lse;
    }
}

// ---------------- launch ----------------
static inline dim3 gemm_grid_f32(int M, int N) {
    return dim3((N + BN - 1) / BN, (M + BM - 1) / BM);
}

extern "C" void kernel_launch(void* const* d_in, const int* in_sizes, int n_in,
                              void* d_out, int out_size) {
    const float* token_feats = (const float*)d_in[0];
    const float* concat_cls  = (const float*)d_in[1];
    const float* W_rel1      = (const float*)d_in[2];
    const float* W_root1     = (const float*)d_in[3];
    const float* b1          = (const float*)d_in[4];
    const float* W_rel2      = (const float*)d_in[5];
    const float* W_root2     = (const float*)d_in[6];
    const float* b2          = (const float*)d_in[7];
    const float* att_w0      = (const float*)d_in[8];
    const float* att_w1      = (const float*)d_in[9];
    const float* lin1_w      = (const float*)d_in[10];
    const float* lin1_b      = (const float*)d_in[11];
    const float* lin2_w      = (const float*)d_in[12];
    const float* lin2_b      = (const float*)d_in[13];
    const int*   wti         = (const int*)d_in[14];
    const int*   eidx        = (const int*)d_in[15];
    const int*   etype       = (const int*)d_in[16];
    const int*   csi         = (const int*)d_in[17];
    float* out = (float*)d_out;

    float *p_x, *p_acc, *p_h, *p_attin, *p_hatt, *p_rep, *p_hid;
    int* p_cnt;
    uint32_t *p_bhi, *p_blo;
    cudaGetSymbolAddress((void**)&p_x,     g_x);
    cudaGetSymbolAddress((void**)&p_acc,   g_acc);
    cudaGetSymbolAddress((void**)&p_h,     g_h);
    cudaGetSymbolAddress((void**)&p_cnt,   g_cnt);
    cudaGetSymbolAddress((void**)&p_attin, g_attin);
    cudaGetSymbolAddress((void**)&p_hatt,  g_hatt);
    cudaGetSymbolAddress((void**)&p_rep,   g_rep);
    cudaGetSymbolAddress((void**)&p_hid,   g_hid);
    cudaGetSymbolAddress((void**)&p_bhi,   g_bhi);
    cudaGetSymbolAddress((void**)&p_blo,   g_blo);

    cudaFuncSetAttribute(gemm_rgcn, cudaFuncAttributeMaxDynamicSharedMemorySize, GSMEM);

    const int T = 256;
    const long long ND = (long long)NN_ * D_;
    const int CVB = KP2_ * D_;
    const dim3 ggrid(D_ / GBN, NN_ / GBM);   // (3, 80)

    // --- graph prep: CSR ---
    zero4_kernel<<<(NR_ / 4 + T - 1) / T, T>>>((float4*)p_cnt, NR_ / 4);
    count_kernel<<<(EE_ + T - 1) / T, T>>>(eidx, etype);
    scan_kernel<<<1, 1024>>>();
    scatter_kernel<<<(EE_ + T - 1) / T, T>>>(eidx, etype);

    // --- x0 ---
    gather_mean_kernel<<<(unsigned)((ND + T - 1) / T), T>>>(token_feats, wti);

    // --- layer 1 ---
    csr_agg_kernel<<<NN_, 192>>>(p_x);
    convertB_kernel<<<(CVB + T - 1) / T, T>>>(W_rel1, W_root1);
    gemm_rgcn<<<ggrid, 256, GSMEM>>>(p_h, p_x, p_bhi, p_blo, b1, p_acc);

    // --- layer 2 ---
    csr_agg_kernel<<<NN_, 192>>>(p_acc);
    convertB_kernel<<<(CVB + T - 1) / T, T>>>(W_rel2, W_root2);
    gemm_rgcn<<<ggrid, 256, GSMEM>>>(p_h, p_acc, p_bhi, p_blo, b2, p_x);

    // --- evidence pooling + attention ---
    ev_pool_kernel<<<(SEQS_ * DOUT_ + T - 1) / T, T>>>();
    build_attin_kernel<<<(SEQS_ * (D_ + 2 * DOUT_) + T - 1) / T, T>>>(token_feats, csi);
    zero4_kernel<<<(SEQS_ * DOUT_ / 4 + T - 1) / T, T>>>((float4*)p_hatt, SEQS_ * DOUT_ / 4);
    sgemm_acc<<<gemm_grid_f32(SEQS_, DOUT_), 256>>>(p_attin, att_w0, p_hatt,
                                                    SEQS_, DOUT_, D_ + 2 * DOUT_);
    relu_kernel<<<(SEQS_ * DOUT_ + T - 1) / T, T>>>(p_hatt, (long long)SEQS_ * DOUT_);
    dotp_kernel<<<SEQS_, 256>>>(att_w1);
    softmax_att_kernel<<<B_, 32>>>(out);

    // --- graph readout + classifier ---
    graph_rep_kernel<<<(B_ * (2 * DOUT_ + D_) + T - 1) / T, T>>>(concat_cls);
    init_bias_kernel<<<(B_ * LH_ + T - 1) / T, T>>>(p_hid, lin1_b, B_, LH_);
    sgemm_acc<<<gemm_grid_f32(B_, LH_), 256>>>(p_rep, lin1_w, p_hid, B_, LH_, 2 * DOUT_ + D_);
    relu_kernel<<<(B_ * LH_ + T - 1) / T, T>>>(p_hid, (long long)B_ * LH_);
    final_kernel<<<B_, 128>>>(lin2_w, lin2_b, out);
}

// round 9
// speedup vs baseline: 1.3948x; 1.1817x over previous
#include <cuda_runtime.h>
#include <cuda_fp16.h>
#include <math.h>
#include <stdint.h>

// ---------------- problem constants ----------------
#define B_      64
#define EVI_    5
#define SEQS_   (B_ * EVI_)          // 320
#define L_      256
#define D_      768
#define WORDS_  32
#define TPW_    4
#define NN_     (SEQS_ * WORDS_)     // 10240 nodes
#define EE_     (NN_ * 16)           // 163840 edges
#define R_      4
#define DOUT_   768
#define LH_     1024
#define NC_     3
#define KTOT_   (5 * D_)             // 3840 fused K
#define NR_     (NN_ * R_)           // 40960 segments
#define KP2_    (KTOT_ / 2)          // 1920 k-pairs

// ---------------- scratch (device globals; no allocs allowed) ----------------
__device__ float    g_x   [(size_t)NN_ * D_];        // x0 / x2
__device__ float    g_acc [(size_t)NN_ * D_];        // x1
__device__ float    g_h   [(size_t)R_ * NN_ * D_];   // per-relation aggregation
__device__ uint32_t g_bhi [(size_t)KP2_ * D_];       // B fp16 k-pair packed [k2][n]
__device__ int      g_cnt [NR_];
__device__ int      g_off [NR_ + 1];
__device__ int      g_cur [NR_];
__device__ int      g_elist[EE_];
__device__ float    g_ev  [SEQS_ * 2 * DOUT_];
__device__ float    g_attin[SEQS_ * (D_ + 2 * DOUT_)];
__device__ float    g_hatt[SEQS_ * DOUT_];
__device__ float    g_p   [SEQS_];
__device__ float    g_a   [SEQS_];
__device__ float    g_rep [B_ * (2 * DOUT_ + D_)];
__device__ float    g_hid [B_ * LH_];

// ---------------- small device helpers ----------------
__device__ __forceinline__ uint32_t smem_u32(const void* p) {
    uint32_t a;
    asm("{ .reg .u64 t; cvta.to.shared.u64 t, %1; cvt.u32.u64 %0, t; }" : "=r"(a) : "l"(p));
    return a;
}
// pack {v0 -> low16, v1 -> high16} as fp16x2
__device__ __forceinline__ uint32_t packh2(float v0, float v1) {
    __half h0 = __float2half_rn(v0);
    __half h1 = __float2half_rn(v1);
    return ((uint32_t)__half_as_ushort(h1) << 16) | (uint32_t)__half_as_ushort(h0);
}
__device__ __forceinline__ void mma16816h(float* c, const uint32_t* a, const uint32_t* b) {
    asm volatile("mma.sync.aligned.m16n8k16.row.col.f32.f16.f16.f32 "
                 "{%0,%1,%2,%3}, {%4,%5,%6,%7}, {%8,%9}, {%0,%1,%2,%3};"
                 : "+f"(c[0]), "+f"(c[1]), "+f"(c[2]), "+f"(c[3])
                 : "r"(a[0]), "r"(a[1]), "r"(a[2]), "r"(a[3]), "r"(b[0]), "r"(b[1]));
}
__device__ __forceinline__ void cp16(uint32_t dst, const void* src) {
    asm volatile("cp.async.cg.shared.global [%0], [%1], 16;" :: "r"(dst), "l"(src));
}

// ---------------- utility kernels ----------------
__global__ void zero4_kernel(float4* p, long long n4) {
    long long t = (long long)blockIdx.x * blockDim.x + threadIdx.x;
    if (t < n4) p[t] = make_float4(0.f, 0.f, 0.f, 0.f);
}
__global__ void relu_kernel(float* p, long long n) {
    long long t = (long long)blockIdx.x * blockDim.x + threadIdx.x;
    if (t < n) p[t] = fmaxf(p[t], 0.f);
}
__global__ void init_bias_kernel(float* C, const float* __restrict__ bias, long long M, int N) {
    long long t = (long long)blockIdx.x * blockDim.x + threadIdx.x;
    if (t < M * N) C[t] = bias[t % N];
}

// ---------------- graph prep: counts -> scan -> scatter (CSR) ----------------
__global__ void count_kernel(const int* __restrict__ eidx, const int* __restrict__ etype) {
    int e = blockIdx.x * blockDim.x + threadIdx.x;
    if (e >= EE_) return;
    atomicAdd(&g_cnt[eidx[EE_ + e] * R_ + etype[e]], 1);
}
__global__ void scan_kernel() {
    __shared__ int part[1024];
    int tid = threadIdx.x;
    int base = tid * 40;
    int s = 0;
#pragma unroll 8
    for (int i = 0; i < 40; ++i) s += g_cnt[base + i];
    part[tid] = s;
    __syncthreads();
    for (int o = 1; o < 1024; o <<= 1) {
        int v = (tid >= o) ? part[tid - o] : 0;
        __syncthreads();
        part[tid] += v;
        __syncthreads();
    }
    int run = tid ? part[tid - 1] : 0;
#pragma unroll 8
    for (int i = 0; i < 40; ++i) {
        int c = g_cnt[base + i];
        g_off[base + i] = run;
        g_cur[base + i] = run;
        run += c;
    }
    if (tid == 1023) g_off[NR_] = run;
}
__global__ void scatter_kernel(const int* __restrict__ eidx, const int* __restrict__ etype) {
    int e = blockIdx.x * blockDim.x + threadIdx.x;
    if (e >= EE_) return;
    int pos = atomicAdd(&g_cur[eidx[EE_ + e] * R_ + etype[e]], 1);
    g_elist[pos] = eidx[e];
}

__global__ void gather_mean_kernel(const float* __restrict__ tok, const int* __restrict__ wti) {
    long long t = (long long)blockIdx.x * blockDim.x + threadIdx.x;
    if (t >= (long long)NN_ * D_) return;
    int n = (int)(t / D_);
    int d = (int)(t % D_);
    const int* w = wti + n * TPW_;
    float s = tok[(size_t)w[0] * D_ + d] + tok[(size_t)w[1] * D_ + d]
            + tok[(size_t)w[2] * D_ + d] + tok[(size_t)w[3] * D_ + d];
    g_x[t] = 0.25f * s;
}

// one CTA per dst node, 192 threads; thread owns 4 feature columns.
__global__ void __launch_bounds__(192)
csr_agg_kernel(const float* __restrict__ x) {
    int dst = blockIdx.x;
    int d = threadIdx.x * 4;
#pragma unroll
    for (int r = 0; r < R_; ++r) {
        int beg = g_off[dst * R_ + r];
        int end = g_off[dst * R_ + r + 1];
        float4 a = make_float4(0.f, 0.f, 0.f, 0.f);
        for (int i = beg; i < end; ++i) {
            int src = g_elist[i];
            float4 v = *(const float4*)(x + (size_t)src * D_ + d);
            a.x += v.x; a.y += v.y; a.z += v.z; a.w += v.w;
        }
        float s = (end > beg) ? (1.f / (float)(end - beg)) : 0.f;
        a.x *= s; a.y *= s; a.z *= s; a.w *= s;
        *(float4*)(g_h + ((size_t)r * NN_ + dst) * D_ + d) = a;
    }
}

// ---------------- B pre-pack: Wcat(3840x768) -> k-pair packed fp16 ----------------
__global__ void convertB_kernel(const float* __restrict__ Wrel, const float* __restrict__ Wroot) {
    int t = blockIdx.x * blockDim.x + threadIdx.x;
    if (t >= KP2_ * D_) return;
    int k2 = t / D_;
    int n  = t - k2 * D_;
    int k  = 2 * k2;
    const float* bp = (k < 4 * D_) ? (Wrel + (size_t)k * D_ + n)
                                   : (Wroot + (size_t)(k - 4 * D_) * D_ + n);
    g_bhi[t] = packh2(bp[0], bp[D_]);
}

// ---------------- fp16 single-pass tensor GEMM: A reg-staged, B cp.async ----------------
// C(NN_ x 768) = relu( [h0|h1|h2|h3|x](NN_ x 3840) @ Wcat + bias )
#define GBM 128
#define GBN 256
#define GBK 32
#define NSTG (KTOT_ / GBK)   // 120
#define AP_  20              // A smem pitch u32 (16 k-pairs + 4 pad)
#define BP_  264             // B smem pitch u32 (256 + 8 pad)
#define ASZ_ (GBM * AP_)     // 2560 u32
#define BSZ_ (16 * BP_)      // 4224 u32
#define SBUF (ASZ_ + BSZ_)           // 6784 u32 per stage
#define GSMEM (2 * SBUF * 4)         // 54272 bytes

__global__ void __launch_bounds__(256, 1)
gemm_rgcn(const float* __restrict__ gh, const float* __restrict__ xroot,
          const uint32_t* __restrict__ Bhi,
          const float* __restrict__ bias, float* __restrict__ C) {
    extern __shared__ uint32_t sm[];
    const uint32_t sb = smem_u32(sm);
    const int tid  = threadIdx.x;
    const int wid  = tid >> 5;
    const int lane = tid & 31;
    const int g    = lane >> 2;
    const int tc   = lane & 3;
    const int wm   = wid & 3;        // 0..3 -> 32-row slice
    const int wn   = wid >> 2;       // 0..1 -> 128-col slice
    const int m0   = blockIdx.y * GBM;
    const int n0   = blockIdx.x * GBN;

    float acc[2][16][4];
#pragma unroll
    for (int i = 0; i < 2; ++i)
#pragma unroll
        for (int j = 0; j < 16; ++j)
#pragma unroll
            for (int q = 0; q < 4; ++q) acc[i][j][q] = 0.f;

    float4 pa[4];

    auto prefetchA = [&](int kc) {
        const int k0 = kc * GBK;
        const int r  = k0 / D_;
        const int d0 = k0 - r * D_;
        const float* Ab = (r < 4) ? (gh + ((size_t)r * NN_ + m0) * D_ + d0)
                                  : (xroot + (size_t)m0 * D_ + d0);
#pragma unroll
        for (int i = 0; i < 4; ++i) {
            int c = tid + i * 256;
            int m = c >> 3, kq = c & 7;
            pa[i] = *(const float4*)(Ab + (size_t)m * D_ + kq * 4);
        }
    };
    auto storeA = [&](uint32_t* buf) {
#pragma unroll
        for (int i = 0; i < 4; ++i) {
            int c = tid + i * 256;
            int m = c >> 3, kq = c & 7;
            float4 v = pa[i];
            uint32_t h0 = packh2(v.x, v.y);
            uint32_t h1 = packh2(v.z, v.w);
            *(uint2*)&buf[m * AP_ + kq * 2] = make_uint2(h0, h1);
        }
    };
    auto issueB = [&](int kc, int buf) {
        const int kp0 = kc * 16;
        const uint32_t bbH = sb + (uint32_t)buf * (SBUF * 4) + ASZ_ * 4;
#pragma unroll
        for (int i = 0; i < 4; ++i) {
            int c = tid + i * 256;
            int row = c >> 6, seg = c & 63;
            size_t gidx = (size_t)(kp0 + row) * D_ + n0 + seg * 4;
            cp16(bbH + row * (BP_ * 4) + seg * 16, Bhi + gidx);
        }
    };
    auto compute = [&](const uint32_t* s) {
        const uint32_t* AsH = s;
        const uint32_t* BsH = s + ASZ_;
#pragma unroll
        for (int ks = 0; ks < 2; ++ks) {
            const int kb = ks * 8;
            uint32_t aH[2][4];
#pragma unroll
            for (int mt = 0; mt < 2; ++mt) {
                int i0 = (wm * 32 + mt * 16 + g) * AP_ + kb + tc;
                int i1 = i0 + 8 * AP_;
                aH[mt][0] = AsH[i0]; aH[mt][1] = AsH[i1];
                aH[mt][2] = AsH[i0 + 4]; aH[mt][3] = AsH[i1 + 4];
            }
#pragma unroll
            for (int ng = 0; ng < 4; ++ng) {
                uint32_t bh[4][2];
#pragma unroll
                for (int q = 0; q < 4; ++q) {
                    int cb = wn * 128 + (ng * 4 + q) * 8;
                    int j0 = (kb + tc) * BP_ + cb + g;
                    int j1 = j0 + 4 * BP_;
                    bh[q][0] = BsH[j0]; bh[q][1] = BsH[j1];
                }
#pragma unroll
                for (int mt = 0; mt < 2; ++mt)
#pragma unroll
                    for (int q = 0; q < 4; ++q)
                        mma16816h(acc[mt][ng * 4 + q], aH[mt], bh[q]);
            }
        }
    };

    // ---- pipeline: A reg double-buffer, B cp.async double-buffer ----
    prefetchA(0);
    storeA(sm);
    issueB(0, 0);
    asm volatile("cp.async.commit_group;" ::: "memory");

#pragma unroll 1
    for (int kc = 0; kc < NSTG; ++kc) {
        const int cur = kc & 1;
        if (kc + 1 < NSTG) {
            issueB(kc + 1, 1 - cur);
            asm volatile("cp.async.commit_group;" ::: "memory");
            prefetchA(kc + 1);
            asm volatile("cp.async.wait_group 1;" ::: "memory");
        } else {
            asm volatile("cp.async.wait_group 0;" ::: "memory");
        }
        __syncthreads();
        compute(sm + cur * SBUF);
        if (kc + 1 < NSTG) storeA(sm + (1 - cur) * SBUF);
        __syncthreads();
    }

    // ---- epilogue: bias + relu ----
#pragma unroll
    for (int mt = 0; mt < 2; ++mt) {
        int row = m0 + wm * 32 + mt * 16 + g;
#pragma unroll
        for (int nt = 0; nt < 16; ++nt) {
            int col = n0 + wn * 128 + nt * 8 + tc * 2;
            float b0 = __ldg(bias + col);
            float b1 = __ldg(bias + col + 1);
            float2 v0 = make_float2(fmaxf(acc[mt][nt][0] + b0, 0.f),
                                    fmaxf(acc[mt][nt][1] + b1, 0.f));
            float2 v1 = make_float2(fmaxf(acc[mt][nt][2] + b0, 0.f),
                                    fmaxf(acc[mt][nt][3] + b1, 0.f));
            *(float2*)(C + (size_t)row * D_ + col)       = v0;
            *(float2*)(C + (size_t)(row + 8) * D_ + col) = v1;
        }
    }
}

// ---------------- fp32 SGEMM for small head GEMMs ----------------
#define BM 128
#define BN 128
#define BK 8
#define TM 8
#define TN 8
__global__ __launch_bounds__(256)
void sgemm_acc(const float* __restrict__ A, const float* __restrict__ Bm,
               float* __restrict__ C, int M, int N, int K) {
    const int brow = blockIdx.y, bcol = blockIdx.x;
    const int tid = threadIdx.x;
    __shared__ float As[BK][BM];
    __shared__ float Bs[BK][BN];
    const int threadRow = tid / (BN / TN);
    const int threadCol = tid % (BN / TN);
    const int aRow = tid >> 1;
    const int aCol = (tid & 1) * 4;
    const int bRow = tid >> 5;
    const int bCol = (tid & 31) * 4;
    float acc[TM][TN] = {};
    float regM[TM], regN[TN];
    const int gARow = brow * BM + aRow;
    const bool aValid = (gARow < M);
    const float* Aptr = A + (size_t)gARow * K;
    const float* Bptr = Bm + bcol * BN;
    for (int k0 = 0; k0 < K; k0 += BK) {
        float4 av = aValid ? *(const float4*)(Aptr + k0 + aCol) : make_float4(0.f, 0.f, 0.f, 0.f);
        As[aCol + 0][aRow] = av.x;
        As[aCol + 1][aRow] = av.y;
        As[aCol + 2][aRow] = av.z;
        As[aCol + 3][aRow] = av.w;
        *(float4*)&Bs[bRow][bCol] = *(const float4*)(Bptr + (size_t)(k0 + bRow) * N + bCol);
        __syncthreads();
#pragma unroll
        for (int k = 0; k < BK; ++k) {
#pragma unroll
            for (int i = 0; i < TM; ++i) regM[i] = As[k][threadRow * TM + i];
#pragma unroll
            for (int j = 0; j < TN; ++j) regN[j] = Bs[k][threadCol * TN + j];
#pragma unroll
            for (int i = 0; i < TM; ++i)
#pragma unroll
                for (int j = 0; j < TN; ++j)
                    acc[i][j] += regM[i] * regN[j];
        }
        __syncthreads();
    }
#pragma unroll
    for (int i = 0; i < TM; ++i) {
        int r = brow * BM + threadRow * TM + i;
        if (r < M) {
            float* Cp = C + (size_t)r * N + bcol * BN + threadCol * TN;
#pragma unroll
            for (int j = 0; j < TN; j += 4) {
                float4 cv = *(float4*)(Cp + j);
                cv.x += acc[i][j + 0];
                cv.y += acc[i][j + 1];
                cv.z += acc[i][j + 2];
                cv.w += acc[i][j + 3];
                *(float4*)(Cp + j) = cv;
            }
        }
    }
}

// ---------------- head kernels ----------------
__global__ void ev_pool_kernel() {
    int t = blockIdx.x * blockDim.x + threadIdx.x;
    if (t >= SEQS_ * DOUT_) return;
    int s = t / DOUT_, d = t % DOUT_;
    const float* base = g_x + (size_t)s * WORDS_ * DOUT_ + d;
    float sum = 0.f, mx = -1e30f;
#pragma unroll 8
    for (int w = 0; w < WORDS_; ++w) {
        float v = base[(size_t)w * DOUT_];
        sum += v;
        mx = fmaxf(mx, v);
    }
    g_ev[s * (2 * DOUT_) + d]         = sum * (1.f / WORDS_);
    g_ev[s * (2 * DOUT_) + DOUT_ + d] = mx;
}
__global__ void build_attin_kernel(const float* __restrict__ tok, const int* __restrict__ csi) {
    int t = blockIdx.x * blockDim.x + threadIdx.x;
    const int W = D_ + 2 * DOUT_;
    if (t >= SEQS_ * W) return;
    int s = t / W, c = t % W;
    if (c < D_) {
        int seq = csi[s / EVI_];
        g_attin[t] = tok[(size_t)seq * L_ * D_ + c];
    } else {
        g_attin[t] = g_ev[s * (2 * DOUT_) + (c - D_)];
    }
}
__global__ void dotp_kernel(const float* __restrict__ att_w1) {
    int s = blockIdx.x;
    int tid = threadIdx.x;
    float acc = 0.f;
    for (int k = tid; k < DOUT_; k += 256)
        acc += g_hatt[(size_t)s * DOUT_ + k] * att_w1[k];
#pragma unroll
    for (int o = 16; o; o >>= 1) acc += __shfl_down_sync(0xffffffffu, acc, o);
    __shared__ float sw[8];
    if ((tid & 31) == 0) sw[tid >> 5] = acc;
    __syncthreads();
    if (tid == 0) {
        float r = 0.f;
#pragma unroll
        for (int w = 0; w < 8; ++w) r += sw[w];
        g_p[s] = r;
    }
}
__global__ void softmax_att_kernel(float* __restrict__ out) {
    int b = blockIdx.x;
    if (threadIdx.x != 0) return;
    float pv[EVI_];
    float m = -1e30f;
#pragma unroll
    for (int e = 0; e < EVI_; ++e) { pv[e] = g_p[b * EVI_ + e]; m = fmaxf(m, pv[e]); }
    float s = 0.f;
#pragma unroll
    for (int e = 0; e < EVI_; ++e) { pv[e] = expf(pv[e] - m); s += pv[e]; }
    float is = 1.f / s;
#pragma unroll
    for (int e = 0; e < EVI_; ++e) {
        g_a[b * EVI_ + e] = pv[e] * is;
        float p = g_p[b * EVI_ + e];
        out[B_ * NC_ + b * EVI_ + e] = 1.f / (1.f + expf(-p));
    }
}
__global__ void graph_rep_kernel(const float* __restrict__ concat_cls) {
    int t = blockIdx.x * blockDim.x + threadIdx.x;
    const int W = 2 * DOUT_ + D_;
    if (t >= B_ * W) return;
    int b = t / W, c = t % W;
    if (c < 2 * DOUT_) {
        float acc = 0.f;
#pragma unroll
        for (int e = 0; e < EVI_; ++e)
            acc += g_a[b * EVI_ + e] * g_ev[(size_t)(b * EVI_ + e) * (2 * DOUT_) + c];
        g_rep[t] = acc;
    } else {
        g_rep[t] = concat_cls[b * D_ + (c - 2 * DOUT_)];
    }
}
__global__ void final_kernel(const float* __restrict__ lin2_w,
                             const float* __restrict__ lin2_b,
                             float* __restrict__ out) {
    int b = blockIdx.x;
    int tid = threadIdx.x;
    float a0 = 0.f, a1 = 0.f, a2 = 0.f;
    for (int k = tid; k < LH_; k += 128) {
        float h = g_hid[(size_t)b * LH_ + k];
        a0 += h * lin2_w[k * NC_ + 0];
        a1 += h * lin2_w[k * NC_ + 1];
        a2 += h * lin2_w[k * NC_ + 2];
    }
#pragma unroll
    for (int o = 16; o; o >>= 1) {
        a0 += __shfl_down_sync(0xffffffffu, a0, o);
        a1 += __shfl_down_sync(0xffffffffu, a1, o);
        a2 += __shfl_down_sync(0xffffffffu, a2, o);
    }
    __shared__ float s0[4], s1[4], s2[4];
    if ((tid & 31) == 0) { int w = tid >> 5; s0[w] = a0; s1[w] = a1; s2[w] = a2; }
    __syncthreads();
    if (tid == 0) {
        float l0 = s0[0] + s0[1] + s0[2] + s0[3] + lin2_b[0];
        float l1 = s1[0] + s1[1] + s1[2] + s1[3] + lin2_b[1];
        float l2 = s2[0] + s2[1] + s2[2] + s2[3] + lin2_b[2];
        float m = fmaxf(l0, fmaxf(l1, l2));
        float lse = logf(expf(l0 - m) + expf(l1 - m) + expf(l2 - m)) + m;
        out[b * NC_ + 0] = l0 - lse;
        out[b * NC_ + 1] = l1 - lse;
        out[b * NC_ + 2] = l2 - lse;
    }
}

// ---------------- launch ----------------
static inline dim3 gemm_grid_f32(int M, int N) {
    return dim3((N + BN - 1) / BN, (M + BM - 1) / BM);
}

extern "C" void kernel_launch(void* const* d_in, const int* in_sizes, int n_in,
                              void* d_out, int out_size) {
    const float* token_feats = (const float*)d_in[0];
    const float* concat_cls  = (const float*)d_in[1];
    const float* W_rel1      = (const float*)d_in[2];
    const float* W_root1     = (const float*)d_in[3];
    const float* b1          = (const float*)d_in[4];
    const float* W_rel2      = (const float*)d_in[5];
    const float* W_root2     = (const float*)d_in[6];
    const float* b2          = (const float*)d_in[7];
    const float* att_w0      = (const float*)d_in[8];
    const float* att_w1      = (const float*)d_in[9];
    const float* lin1_w      = (const float*)d_in[10];
    const float* lin1_b      = (const float*)d_in[11];
    const float* lin2_w      = (const float*)d_in[12];
    const float* lin2_b      = (const float*)d_in[13];
    const int*   wti         = (const int*)d_in[14];
    const int*   eidx        = (const int*)d_in[15];
    const int*   etype       = (const int*)d_in[16];
    const int*   csi         = (const int*)d_in[17];
    float* out = (float*)d_out;

    float *p_x, *p_acc, *p_h, *p_attin, *p_hatt, *p_rep, *p_hid;
    int* p_cnt;
    uint32_t *p_bhi;
    cudaGetSymbolAddress((void**)&p_x,     g_x);
    cudaGetSymbolAddress((void**)&p_acc,   g_acc);
    cudaGetSymbolAddress((void**)&p_h,     g_h);
    cudaGetSymbolAddress((void**)&p_cnt,   g_cnt);
    cudaGetSymbolAddress((void**)&p_attin, g_attin);
    cudaGetSymbolAddress((void**)&p_hatt,  g_hatt);
    cudaGetSymbolAddress((void**)&p_rep,   g_rep);
    cudaGetSymbolAddress((void**)&p_hid,   g_hid);
    cudaGetSymbolAddress((void**)&p_bhi,   g_bhi);

    cudaFuncSetAttribute(gemm_rgcn, cudaFuncAttributeMaxDynamicSharedMemorySize, GSMEM);

    const int T = 256;
    const long long ND = (long long)NN_ * D_;
    const int CVB = KP2_ * D_;
    const dim3 ggrid(D_ / GBN, NN_ / GBM);   // (3, 80)

    // --- graph prep: CSR ---
    zero4_kernel<<<(NR_ / 4 + T - 1) / T, T>>>((float4*)p_cnt, NR_ / 4);
    count_kernel<<<(EE_ + T - 1) / T, T>>>(eidx, etype);
    scan_kernel<<<1, 1024>>>();
    scatter_kernel<<<(EE_ + T - 1) / T, T>>>(eidx, etype);

    // --- x0 ---
    gather_mean_kernel<<<(unsigned)((ND + T - 1) / T), T>>>(token_feats, wti);

    // --- layer 1 ---
    csr_agg_kernel<<<NN_, 192>>>(p_x);
    convertB_kernel<<<(CVB + T - 1) / T, T>>>(W_rel1, W_root1);
    gemm_rgcn<<<ggrid, 256, GSMEM>>>(p_h, p_x, p_bhi, b1, p_acc);

    // --- layer 2 ---
    csr_agg_kernel<<<NN_, 192>>>(p_acc);
    convertB_kernel<<<(CVB + T - 1) / T, T>>>(W_rel2, W_root2);
    gemm_rgcn<<<ggrid, 256, GSMEM>>>(p_h, p_acc, p_bhi, b2, p_x);

    // --- evidence pooling + attention ---
    ev_pool_kernel<<<(SEQS_ * DOUT_ + T - 1) / T, T>>>();
    build_attin_kernel<<<(SEQS_ * (D_ + 2 * DOUT_) + T - 1) / T, T>>>(token_feats, csi);
    zero4_kernel<<<(SEQS_ * DOUT_ / 4 + T - 1) / T, T>>>((float4*)p_hatt, SEQS_ * DOUT_ / 4);
    sgemm_acc<<<gemm_grid_f32(SEQS_, DOUT_), 256>>>(p_attin, att_w0, p_hatt,
                                                    SEQS_, DOUT_, D_ + 2 * DOUT_);
    relu_kernel<<<(SEQS_ * DOUT_ + T - 1) / T, T>>>(p_hatt, (long long)SEQS_ * DOUT_);
    dotp_kernel<<<SEQS_, 256>>>(att_w1);
    softmax_att_kernel<<<B_, 32>>>(out);

    // --- graph readout + classifier ---
    graph_rep_kernel<<<(B_ * (2 * DOUT_ + D_) + T - 1) / T, T>>>(concat_cls);
    init_bias_kernel<<<(B_ * LH_ + T - 1) / T, T>>>(p_hid, lin1_b, B_, LH_);
    sgemm_acc<<<gemm_grid_f32(B_, LH_), 256>>>(p_rep, lin1_w, p_hid, B_, LH_, 2 * DOUT_ + D_);
    relu_kernel<<<(B_ * LH_ + T - 1) / T, T>>>(p_hid, (long long)B_ * LH_);
    final_kernel<<<B_, 128>>>(lin2_w, lin2_b, out);
}

// round 10
// speedup vs baseline: 2.9881x; 2.1423x over previous
#include <cuda_runtime.h>
#include <cuda_fp16.h>
#include <math.h>
#include <stdint.h>

// ---------------- problem constants ----------------
#define B_      64
#define EVI_    5
#define SEQS_   (B_ * EVI_)          // 320
#define L_      256
#define D_      768
#define D2_     (D_ / 2)             // 384 u32 per fp16-pair row
#define WORDS_  32
#define TPW_    4
#define NN_     (SEQS_ * WORDS_)     // 10240 nodes
#define EE_     (NN_ * 16)           // 163840 edges
#define R_      4
#define DOUT_   768
#define LH_     1024
#define NC_     3
#define KTOT_   (5 * D_)             // 3840 fused K
#define NR_     (NN_ * R_)           // 40960 segments
#define KP2_    (KTOT_ / 2)          // 1920 k-pairs

// ---------------- scratch (device globals; no allocs allowed) ----------------
__device__ float    g_x   [(size_t)NN_ * D_];        // x0 / x2 (fp32)
__device__ float    g_acc [(size_t)NN_ * D_];        // x1 (fp32)
__device__ uint32_t g_hh  [(size_t)R_ * NN_ * D2_];  // fp16 h, k-pair packed
__device__ uint32_t g_xh  [(size_t)NN_ * D2_];       // fp16 x0
__device__ uint32_t g_yh  [(size_t)NN_ * D2_];       // fp16 x1
__device__ uint32_t g_bh  [(size_t)KP2_ * D_];       // fp16 Wcat k-pair packed [k2][n]
__device__ int      g_cnt [NR_];
__device__ int      g_off [NR_ + 1];
__device__ int      g_cur [NR_];
__device__ int      g_elist[EE_];
__device__ float    g_ev  [SEQS_ * 2 * DOUT_];
__device__ float    g_attin[SEQS_ * (D_ + 2 * DOUT_)];
__device__ float    g_hatt[SEQS_ * DOUT_];
__device__ float    g_p   [SEQS_];
__device__ float    g_a   [SEQS_];
__device__ float    g_rep [B_ * (2 * DOUT_ + D_)];
__device__ float    g_hid [B_ * LH_];

// ---------------- small device helpers ----------------
__device__ __forceinline__ uint32_t smem_u32(const void* p) {
    uint32_t a;
    asm("{ .reg .u64 t; cvta.to.shared.u64 t, %1; cvt.u32.u64 %0, t; }" : "=r"(a) : "l"(p));
    return a;
}
__device__ __forceinline__ uint32_t packh2(float v0, float v1) {
    __half h0 = __float2half_rn(v0);
    __half h1 = __float2half_rn(v1);
    return ((uint32_t)__half_as_ushort(h1) << 16) | (uint32_t)__half_as_ushort(h0);
}
__device__ __forceinline__ void mma16816h(float* c, const uint32_t* a, const uint32_t* b) {
    asm volatile("mma.sync.aligned.m16n8k16.row.col.f32.f16.f16.f32 "
                 "{%0,%1,%2,%3}, {%4,%5,%6,%7}, {%8,%9}, {%0,%1,%2,%3};"
                 : "+f"(c[0]), "+f"(c[1]), "+f"(c[2]), "+f"(c[3])
                 : "r"(a[0]), "r"(a[1]), "r"(a[2]), "r"(a[3]), "r"(b[0]), "r"(b[1]));
}
__device__ __forceinline__ void cp16(uint32_t dst, const void* src) {
    asm volatile("cp.async.cg.shared.global [%0], [%1], 16;" :: "r"(dst), "l"(src));
}
__device__ __forceinline__ void red4(float* p, float a, float b, float c, float d) {
    asm volatile("red.global.add.v4.f32 [%0], {%1,%2,%3,%4};"
                 :: "l"(p), "f"(a), "f"(b), "f"(c), "f"(d) : "memory");
}

// ---------------- utility kernels ----------------
__global__ void zero4_kernel(float4* p, long long n4) {
    long long t = (long long)blockIdx.x * blockDim.x + threadIdx.x;
    if (t < n4) p[t] = make_float4(0.f, 0.f, 0.f, 0.f);
}
__global__ void relu_kernel(float* p, long long n) {
    long long t = (long long)blockIdx.x * blockDim.x + threadIdx.x;
    if (t < n) p[t] = fmaxf(p[t], 0.f);
}
__global__ void init_bias_kernel(float* C, const float* __restrict__ bias, long long M, int N) {
    long long t = (long long)blockIdx.x * blockDim.x + threadIdx.x;
    if (t < M * N) C[t] = bias[t % N];
}

// ---------------- graph prep: counts -> scan -> scatter (CSR) ----------------
__global__ void count_kernel(const int* __restrict__ eidx, const int* __restrict__ etype) {
    int e = blockIdx.x * blockDim.x + threadIdx.x;
    if (e >= EE_) return;
    atomicAdd(&g_cnt[eidx[EE_ + e] * R_ + etype[e]], 1);
}
__global__ void scan_kernel() {
    __shared__ int part[1024];
    int tid = threadIdx.x;
    int base = tid * 40;
    int s = 0;
#pragma unroll 8
    for (int i = 0; i < 40; ++i) s += g_cnt[base + i];
    part[tid] = s;
    __syncthreads();
    for (int o = 1; o < 1024; o <<= 1) {
        int v = (tid >= o) ? part[tid - o] : 0;
        __syncthreads();
        part[tid] += v;
        __syncthreads();
    }
    int run = tid ? part[tid - 1] : 0;
#pragma unroll 8
    for (int i = 0; i < 40; ++i) {
        int c = g_cnt[base + i];
        g_off[base + i] = run;
        g_cur[base + i] = run;
        run += c;
    }
    if (tid == 1023) g_off[NR_] = run;
}
__global__ void scatter_kernel(const int* __restrict__ eidx, const int* __restrict__ etype) {
    int e = blockIdx.x * blockDim.x + threadIdx.x;
    if (e >= EE_) return;
    int pos = atomicAdd(&g_cur[eidx[EE_ + e] * R_ + etype[e]], 1);
    g_elist[pos] = eidx[e];
}

// x0 fp32 + fp16 pack; thread owns a column pair
__global__ void gather_mean_kernel(const float* __restrict__ tok, const int* __restrict__ wti) {
    long long t = (long long)blockIdx.x * blockDim.x + threadIdx.x;
    if (t >= (long long)NN_ * D2_) return;
    int n = (int)(t / D2_);
    int d = (int)(t % D2_) * 2;
    const int* w = wti + n * TPW_;
    float v0 = 0.f, v1 = 0.f;
#pragma unroll
    for (int i = 0; i < TPW_; ++i) {
        const float* r = tok + (size_t)w[i] * D_ + d;
        v0 += r[0]; v1 += r[1];
    }
    v0 *= 0.25f; v1 *= 0.25f;
    *(float2*)(g_x + (size_t)n * D_ + d) = make_float2(v0, v1);
    g_xh[t] = packh2(v0, v1);
}

// one CTA per dst node, 192 threads; thread owns 4 feature columns; writes fp16 h.
__global__ void __launch_bounds__(192)
csr_agg_kernel(const float* __restrict__ x) {
    int dst = blockIdx.x;
    int d = threadIdx.x * 4;
#pragma unroll
    for (int r = 0; r < R_; ++r) {
        int beg = g_off[dst * R_ + r];
        int end = g_off[dst * R_ + r + 1];
        float4 a = make_float4(0.f, 0.f, 0.f, 0.f);
        for (int i = beg; i < end; ++i) {
            int src = g_elist[i];
            float4 v = *(const float4*)(x + (size_t)src * D_ + d);
            a.x += v.x; a.y += v.y; a.z += v.z; a.w += v.w;
        }
        float s = (end > beg) ? (1.f / (float)(end - beg)) : 0.f;
        a.x *= s; a.y *= s; a.z *= s; a.w *= s;
        size_t o = ((size_t)r * NN_ + dst) * D2_ + threadIdx.x * 2;
        *(uint2*)&g_hh[o] = make_uint2(packh2(a.x, a.y), packh2(a.z, a.w));
    }
}

// Wcat(3840x768) -> k-pair packed fp16
__global__ void convertB_kernel(const float* __restrict__ Wrel, const float* __restrict__ Wroot) {
    int t = blockIdx.x * blockDim.x + threadIdx.x;
    if (t >= KP2_ * D_) return;
    int k2 = t / D_;
    int n  = t - k2 * D_;
    int k  = 2 * k2;
    const float* bp = (k < 4 * D_) ? (Wrel + (size_t)k * D_ + n)
                                   : (Wroot + (size_t)(k - 4 * D_) * D_ + n);
    g_bh[t] = packh2(bp[0], bp[D_]);
}

// ---------------- fp16 single-pass tensor GEMM: A + B both cp.async ----------------
// C(NN_ x 768) = relu( [h0|h1|h2|h3|x](NN_ x 3840) @ Wcat + bias ); optional fp16 copy out.
#define GBM 128
#define GBN 256
#define GBK 32
#define NSTG (KTOT_ / GBK)   // 120
#define AP_  20              // A smem pitch u32 (16 k-pairs + 4 pad)
#define BP_  264             // B smem pitch u32 (256 + 8 pad)
#define ASZ_ (GBM * AP_)     // 2560 u32
#define BSZ_ (16 * BP_)      // 4224 u32
#define SBUF (ASZ_ + BSZ_)           // 6784 u32 per stage
#define GSMEM (2 * SBUF * 4)         // 54272 bytes

__global__ void __launch_bounds__(256, 1)
gemm_rgcn(const uint32_t* __restrict__ Hh, const uint32_t* __restrict__ Xh,
          const uint32_t* __restrict__ Bh,
          const float* __restrict__ bias, float* __restrict__ C,
          uint32_t* __restrict__ Yh) {
    extern __shared__ uint32_t sm[];
    const uint32_t sb = smem_u32(sm);
    const int tid  = threadIdx.x;
    const int wid  = tid >> 5;
    const int lane = tid & 31;
    const int g    = lane >> 2;
    const int tc   = lane & 3;
    const int wm   = wid & 3;        // 0..3 -> 32-row slice
    const int wn   = wid >> 2;       // 0..1 -> 128-col slice
    const int m0   = blockIdx.y * GBM;
    const int n0   = blockIdx.x * GBN;

    float acc[2][16][4];
#pragma unroll
    for (int i = 0; i < 2; ++i)
#pragma unroll
        for (int j = 0; j < 16; ++j)
#pragma unroll
            for (int q = 0; q < 4; ++q) acc[i][j][q] = 0.f;

    auto issueA = [&](int kc, int buf) {
        const int k0 = kc * GBK;
        const int r  = k0 / D_;
        const int dq = (k0 - r * D_) >> 1;
        const uint32_t* src = (r < 4) ? (Hh + ((size_t)r * NN_ + m0) * D2_ + dq)
                                      : (Xh + (size_t)m0 * D2_ + dq);
        const uint32_t aB = sb + (uint32_t)buf * (SBUF * 4);
#pragma unroll
        for (int i = 0; i < 2; ++i) {
            int c = tid + i * 256;
            int row = c >> 2, seg = c & 3;
            cp16(aB + row * (AP_ * 4) + seg * 16, src + (size_t)row * D2_ + seg * 4);
        }
    };
    auto issueB = [&](int kc, int buf) {
        const int kp0 = kc * 16;
        const uint32_t bbH = sb + (uint32_t)buf * (SBUF * 4) + ASZ_ * 4;
#pragma unroll
        for (int i = 0; i < 4; ++i) {
            int c = tid + i * 256;
            int row = c >> 6, seg = c & 63;
            size_t gidx = (size_t)(kp0 + row) * D_ + n0 + seg * 4;
            cp16(bbH + row * (BP_ * 4) + seg * 16, Bh + gidx);
        }
    };
    auto compute = [&](const uint32_t* s) {
        const uint32_t* AsH = s;
        const uint32_t* BsH = s + ASZ_;
#pragma unroll
        for (int ks = 0; ks < 2; ++ks) {
            const int kb = ks * 8;
            uint32_t aH[2][4];
#pragma unroll
            for (int mt = 0; mt < 2; ++mt) {
                int i0 = (wm * 32 + mt * 16 + g) * AP_ + kb + tc;
                int i1 = i0 + 8 * AP_;
                aH[mt][0] = AsH[i0]; aH[mt][1] = AsH[i1];
                aH[mt][2] = AsH[i0 + 4]; aH[mt][3] = AsH[i1 + 4];
            }
#pragma unroll
            for (int ng = 0; ng < 4; ++ng) {
                uint32_t bh[4][2];
#pragma unroll
                for (int q = 0; q < 4; ++q) {
                    int cb = wn * 128 + (ng * 4 + q) * 8;
                    int j0 = (kb + tc) * BP_ + cb + g;
                    int j1 = j0 + 4 * BP_;
                    bh[q][0] = BsH[j0]; bh[q][1] = BsH[j1];
                }
#pragma unroll
                for (int mt = 0; mt < 2; ++mt)
#pragma unroll
                    for (int q = 0; q < 4; ++q)
                        mma16816h(acc[mt][ng * 4 + q], aH[mt], bh[q]);
            }
        }
    };

    issueA(0, 0); issueB(0, 0);
    asm volatile("cp.async.commit_group;" ::: "memory");

#pragma unroll 1
    for (int kc = 0; kc < NSTG; ++kc) {
        const int cur = kc & 1;
        if (kc + 1 < NSTG) {
            issueA(kc + 1, 1 - cur);
            issueB(kc + 1, 1 - cur);
            asm volatile("cp.async.commit_group;" ::: "memory");
            asm volatile("cp.async.wait_group 1;" ::: "memory");
        } else {
            asm volatile("cp.async.wait_group 0;" ::: "memory");
        }
        __syncthreads();
        compute(sm + cur * SBUF);
        __syncthreads();
    }

    // ---- epilogue: bias + relu (+ optional fp16 copy) ----
#pragma unroll
    for (int mt = 0; mt < 2; ++mt) {
        int row = m0 + wm * 32 + mt * 16 + g;
#pragma unroll
        for (int nt = 0; nt < 16; ++nt) {
            int col = n0 + wn * 128 + nt * 8 + tc * 2;
            float b0 = __ldg(bias + col);
            float b1 = __ldg(bias + col + 1);
            float2 v0 = make_float2(fmaxf(acc[mt][nt][0] + b0, 0.f),
                                    fmaxf(acc[mt][nt][1] + b1, 0.f));
            float2 v1 = make_float2(fmaxf(acc[mt][nt][2] + b0, 0.f),
                                    fmaxf(acc[mt][nt][3] + b1, 0.f));
            *(float2*)(C + (size_t)row * D_ + col)       = v0;
            *(float2*)(C + (size_t)(row + 8) * D_ + col) = v1;
            if (Yh) {
                Yh[(size_t)row * D2_ + (col >> 1)]       = packh2(v0.x, v0.y);
                Yh[(size_t)(row + 8) * D2_ + (col >> 1)] = packh2(v1.x, v1.y);
            }
        }
    }
}

// ---------------- split-K fp32 GEMM for head ops: C += A(MxK)@B(KxN) over k-chunk ----------------
// grid: (N/64, ceil(M/64), K/kchunk); C must be pre-initialized (bias or zero).
#define HB 64
#define HK 16
__global__ void __launch_bounds__(256)
sgemm_splitk(const float* __restrict__ A, const float* __restrict__ Bm,
             float* __restrict__ C, int M, int N, int K, int kchunk) {
    __shared__ float As[HK][HB + 4];
    __shared__ float Bs[HK][HB + 4];
    const int tid = threadIdx.x;
    const int tr = tid >> 4;        // 0..15
    const int tcol = tid & 15;      // 0..15
    const int m0 = blockIdx.y * HB;
    const int n0 = blockIdx.x * HB;
    const int k0 = blockIdx.z * kchunk;
    const int ar = tid >> 2, ac = (tid & 3) * 4;   // A: 64 rows x 16 k
    const int br = tid >> 4, bc = (tid & 15) * 4;  // B: 16 k x 64 n
    float acc[4][4] = {};
    for (int kk = 0; kk < kchunk; kk += HK) {
        int k = k0 + kk;
        float4 av = (m0 + ar < M) ? *(const float4*)(A + (size_t)(m0 + ar) * K + k + ac)
                                  : make_float4(0.f, 0.f, 0.f, 0.f);
        As[ac + 0][ar] = av.x;
        As[ac + 1][ar] = av.y;
        As[ac + 2][ar] = av.z;
        As[ac + 3][ar] = av.w;
        *(float4*)&Bs[br][bc] = *(const float4*)(Bm + (size_t)(k + br) * N + n0 + bc);
        __syncthreads();
#pragma unroll
        for (int kq = 0; kq < HK; ++kq) {
            float rm[4], rn[4];
#pragma unroll
            for (int i = 0; i < 4; ++i) rm[i] = As[kq][tr * 4 + i];
#pragma unroll
            for (int j = 0; j < 4; ++j) rn[j] = Bs[kq][tcol * 4 + j];
#pragma unroll
            for (int i = 0; i < 4; ++i)
#pragma unroll
                for (int j = 0; j < 4; ++j)
                    acc[i][j] += rm[i] * rn[j];
        }
        __syncthreads();
    }
#pragma unroll
    for (int i = 0; i < 4; ++i) {
        int row = m0 + tr * 4 + i;
        if (row < M)
            red4(C + (size_t)row * N + n0 + tcol * 4,
                 acc[i][0], acc[i][1], acc[i][2], acc[i][3]);
    }
}

// ---------------- head kernels ----------------
__global__ void ev_pool_kernel() {
    int t = blockIdx.x * blockDim.x + threadIdx.x;
    if (t >= SEQS_ * DOUT_) return;
    int s = t / DOUT_, d = t % DOUT_;
    const float* base = g_x + (size_t)s * WORDS_ * DOUT_ + d;
    float sum = 0.f, mx = -1e30f;
#pragma unroll 8
    for (int w = 0; w < WORDS_; ++w) {
        float v = base[(size_t)w * DOUT_];
        sum += v;
        mx = fmaxf(mx, v);
    }
    g_ev[s * (2 * DOUT_) + d]         = sum * (1.f / WORDS_);
    g_ev[s * (2 * DOUT_) + DOUT_ + d] = mx;
}
__global__ void build_attin_kernel(const float* __restrict__ tok, const int* __restrict__ csi) {
    int t = blockIdx.x * blockDim.x + threadIdx.x;
    const int W = D_ + 2 * DOUT_;
    if (t >= SEQS_ * W) return;
    int s = t / W, c = t % W;
    if (c < D_) {
        int seq = csi[s / EVI_];
        g_attin[t] = tok[(size_t)seq * L_ * D_ + c];
    } else {
        g_attin[t] = g_ev[s * (2 * DOUT_) + (c - D_)];
    }
}
__global__ void dotp_kernel(const float* __restrict__ att_w1) {
    int s = blockIdx.x;
    int tid = threadIdx.x;
    float acc = 0.f;
    for (int k = tid; k < DOUT_; k += 256) {
        float h = g_hatt[(size_t)s * DOUT_ + k];
        acc += fmaxf(h, 0.f) * att_w1[k];
    }
#pragma unroll
    for (int o = 16; o; o >>= 1) acc += __shfl_down_sync(0xffffffffu, acc, o);
    __shared__ float sw[8];
    if ((tid & 31) == 0) sw[tid >> 5] = acc;
    __syncthreads();
    if (tid == 0) {
        float r = 0.f;
#pragma unroll
        for (int w = 0; w < 8; ++w) r += sw[w];
        g_p[s] = r;
    }
}
__global__ void softmax_att_kernel(float* __restrict__ out) {
    int b = blockIdx.x;
    if (threadIdx.x != 0) return;
    float pv[EVI_];
    float m = -1e30f;
#pragma unroll
    for (int e = 0; e < EVI_; ++e) { pv[e] = g_p[b * EVI_ + e]; m = fmaxf(m, pv[e]); }
    float s = 0.f;
#pragma unroll
    for (int e = 0; e < EVI_; ++e) { pv[e] = expf(pv[e] - m); s += pv[e]; }
    float is = 1.f / s;
#pragma unroll
    for (int e = 0; e < EVI_; ++e) {
        g_a[b * EVI_ + e] = pv[e] * is;
        float p = g_p[b * EVI_ + e];
        out[B_ * NC_ + b * EVI_ + e] = 1.f / (1.f + expf(-p));
    }
}
__global__ void graph_rep_kernel(const float* __restrict__ concat_cls) {
    int t = blockIdx.x * blockDim.x + threadIdx.x;
    const int W = 2 * DOUT_ + D_;
    if (t >= B_ * W) return;
    int b = t / W, c = t % W;
    if (c < 2 * DOUT_) {
        float acc = 0.f;
#pragma unroll
        for (int e = 0; e < EVI_; ++e)
            acc += g_a[b * EVI_ + e] * g_ev[(size_t)(b * EVI_ + e) * (2 * DOUT_) + c];
        g_rep[t] = acc;
    } else {
        g_rep[t] = concat_cls[b * D_ + (c - 2 * DOUT_)];
    }
}
__global__ void final_kernel(const float* __restrict__ lin2_w,
                             const float* __restrict__ lin2_b,
                             float* __restrict__ out) {
    int b = blockIdx.x;
    int tid = threadIdx.x;
    float a0 = 0.f, a1 = 0.f, a2 = 0.f;
    for (int k = tid; k < LH_; k += 128) {
        float h = fmaxf(g_hid[(size_t)b * LH_ + k], 0.f);
        a0 += h * lin2_w[k * NC_ + 0];
        a1 += h * lin2_w[k * NC_ + 1];
        a2 += h * lin2_w[k * NC_ + 2];
    }
#pragma unroll
    for (int o = 16; o; o >>= 1) {
        a0 += __shfl_down_sync(0xffffffffu, a0, o);
        a1 += __shfl_down_sync(0xffffffffu, a1, o);
        a2 += __shfl_down_sync(0xffffffffu, a2, o);
    }
    __shared__ float s0[4], s1[4], s2[4];
    if ((tid & 31) == 0) { int w = tid >> 5; s0[w] = a0; s1[w] = a1; s2[w] = a2; }
    __syncthreads();
    if (tid == 0) {
        float l0 = s0[0] + s0[1] + s0[2] + s0[3] + lin2_b[0];
        float l1 = s1[0] + s1[1] + s1[2] + s1[3] + lin2_b[1];
        float l2 = s2[0] + s2[1] + s2[2] + s2[3] + lin2_b[2];
        float m = fmaxf(l0, fmaxf(l1, l2));
        float lse = logf(expf(l0 - m) + expf(l1 - m) + expf(l2 - m)) + m;
        out[b * NC_ + 0] = l0 - lse;
        out[b * NC_ + 1] = l1 - lse;
        out[b * NC_ + 2] = l2 - lse;
    }
}

// ---------------- launch ----------------
extern "C" void kernel_launch(void* const* d_in, const int* in_sizes, int n_in,
                              void* d_out, int out_size) {
    const float* token_feats = (const float*)d_in[0];
    const float* concat_cls  = (const float*)d_in[1];
    const float* W_rel1      = (const float*)d_in[2];
    const float* W_root1     = (const float*)d_in[3];
    const float* b1          = (const float*)d_in[4];
    const float* W_rel2      = (const float*)d_in[5];
    const float* W_root2     = (const float*)d_in[6];
    const float* b2          = (const float*)d_in[7];
    const float* att_w0      = (const float*)d_in[8];
    const float* att_w1      = (const float*)d_in[9];
    const float* lin1_w      = (const float*)d_in[10];
    const float* lin1_b      = (const float*)d_in[11];
    const float* lin2_w      = (const float*)d_in[12];
    const float* lin2_b      = (const float*)d_in[13];
    const int*   wti         = (const int*)d_in[14];
    const int*   eidx        = (const int*)d_in[15];
    const int*   etype       = (const int*)d_in[16];
    const int*   csi         = (const int*)d_in[17];
    float* out = (float*)d_out;

    float *p_x, *p_acc, *p_attin, *p_hatt, *p_rep, *p_hid;
    int* p_cnt;
    uint32_t *p_hh, *p_xh, *p_yh, *p_bh;
    cudaGetSymbolAddress((void**)&p_x,     g_x);
    cudaGetSymbolAddress((void**)&p_acc,   g_acc);
    cudaGetSymbolAddress((void**)&p_cnt,   g_cnt);
    cudaGetSymbolAddress((void**)&p_attin, g_attin);
    cudaGetSymbolAddress((void**)&p_hatt,  g_hatt);
    cudaGetSymbolAddress((void**)&p_rep,   g_rep);
    cudaGetSymbolAddress((void**)&p_hid,   g_hid);
    cudaGetSymbolAddress((void**)&p_hh,    g_hh);
    cudaGetSymbolAddress((void**)&p_xh,    g_xh);
    cudaGetSymbolAddress((void**)&p_yh,    g_yh);
    cudaGetSymbolAddress((void**)&p_bh,    g_bh);

    cudaFuncSetAttribute(gemm_rgcn, cudaFuncAttributeMaxDynamicSharedMemorySize, GSMEM);

    const int T = 256;
    const long long NQ = (long long)NN_ * D2_;
    const int CVB = KP2_ * D_;
    const dim3 ggrid(D_ / GBN, NN_ / GBM);   // (3, 80)
    const int HKW = D_ + 2 * DOUT_;          // 2304

    // --- graph prep: CSR ---
    zero4_kernel<<<(NR_ / 4 + T - 1) / T, T>>>((float4*)p_cnt, NR_ / 4);
    count_kernel<<<(EE_ + T - 1) / T, T>>>(eidx, etype);
    scan_kernel<<<1, 1024>>>();
    scatter_kernel<<<(EE_ + T - 1) / T, T>>>(eidx, etype);

    // --- x0 (fp32 + fp16) ---
    gather_mean_kernel<<<(unsigned)((NQ + T - 1) / T), T>>>(token_feats, wti);

    // --- layer 1 ---
    csr_agg_kernel<<<NN_, 192>>>(p_x);
    convertB_kernel<<<(CVB + T - 1) / T, T>>>(W_rel1, W_root1);
    gemm_rgcn<<<ggrid, 256, GSMEM>>>(p_hh, p_xh, p_bh, b1, p_acc, p_yh);

    // --- layer 2 ---
    csr_agg_kernel<<<NN_, 192>>>(p_acc);
    convertB_kernel<<<(CVB + T - 1) / T, T>>>(W_rel2, W_root2);
    gemm_rgcn<<<ggrid, 256, GSMEM>>>(p_hh, p_yh, p_bh, b2, p_x, nullptr);

    // --- evidence pooling + attention ---
    ev_pool_kernel<<<(SEQS_ * DOUT_ + T - 1) / T, T>>>();
    build_attin_kernel<<<(SEQS_ * HKW + T - 1) / T, T>>>(token_feats, csi);
    zero4_kernel<<<(SEQS_ * DOUT_ / 4 + T - 1) / T, T>>>((float4*)p_hatt, SEQS_ * DOUT_ / 4);
    // attention GEMM: (320 x 768) = attin(320 x 2304) @ att_w0 ; relu fused into dotp
    {
        dim3 hg(DOUT_ / HB, (SEQS_ + HB - 1) / HB, 8);   // (12, 5, 8), kchunk=288
        sgemm_splitk<<<hg, 256>>>(p_attin, att_w0, p_hatt, SEQS_, DOUT_, HKW, HKW / 8);
    }
    dotp_kernel<<<SEQS_, 256>>>(att_w1);
    softmax_att_kernel<<<B_, 32>>>(out);

    // --- graph readout + classifier ---
    graph_rep_kernel<<<(B_ * HKW + T - 1) / T, T>>>(concat_cls);
    init_bias_kernel<<<(B_ * LH_ + T - 1) / T, T>>>(p_hid, lin1_b, B_, LH_);
    {
        dim3 hg(LH_ / HB, (B_ + HB - 1) / HB, 8);        // (16, 1, 8), kchunk=288
        sgemm_splitk<<<hg, 256>>>(p_rep, lin1_w, p_hid, B_, LH_, HKW, HKW / 8);
    }
    final_kernel<<<B_, 128>>>(lin2_w, lin2_b, out);   // relu fused inside
}

// round 11
// speedup vs baseline: 3.0264x; 1.0128x over previous
#include <cuda_runtime.h>
#include <cuda_fp16.h>
#include <math.h>
#include <stdint.h>

// ---------------- problem constants ----------------
#define B_      64
#define EVI_    5
#define SEQS_   (B_ * EVI_)          // 320
#define L_      256
#define D_      768
#define D2_     (D_ / 2)             // 384 u32 per fp16-pair row
#define WORDS_  32
#define TPW_    4
#define NN_     (SEQS_ * WORDS_)     // 10240 nodes
#define EE_     (NN_ * 16)           // 163840 edges
#define R_      4
#define DOUT_   768
#define LH_     1024
#define NC_     3
#define KTOT_   (5 * D_)             // 3840 fused K
#define NR_     (NN_ * R_)           // 40960 segments
#define KP2_    (KTOT_ / 2)          // 1920 k-pairs

// ---------------- scratch (device globals; no allocs allowed) ----------------
__device__ float    g_x   [(size_t)NN_ * D_];        // x2 (fp32, layer-2 out for head)
__device__ uint32_t g_hh  [(size_t)R_ * NN_ * D2_];  // fp16 h, k-pair packed
__device__ uint32_t g_xh  [(size_t)NN_ * D2_];       // fp16 x0
__device__ uint32_t g_yh  [(size_t)NN_ * D2_];       // fp16 x1
__device__ uint32_t g_bh  [(size_t)KP2_ * D_];       // fp16 Wcat k-pair packed [k2][n]
__device__ int      g_cnt [NR_];
__device__ int      g_off [NR_ + 1];
__device__ int      g_cur [NR_];
__device__ int      g_elist[EE_];
__device__ float    g_ev  [SEQS_ * 2 * DOUT_];
__device__ float    g_attin[SEQS_ * (D_ + 2 * DOUT_)];
__device__ float    g_hatt[SEQS_ * DOUT_];
__device__ float    g_p   [SEQS_];
__device__ float    g_a   [SEQS_];
__device__ float    g_rep [B_ * (2 * DOUT_ + D_)];
__device__ float    g_hid [B_ * LH_];

// ---------------- small device helpers ----------------
__device__ __forceinline__ uint32_t smem_u32(const void* p) {
    uint32_t a;
    asm("{ .reg .u64 t; cvta.to.shared.u64 t, %1; cvt.u32.u64 %0, t; }" : "=r"(a) : "l"(p));
    return a;
}
__device__ __forceinline__ uint32_t packh2(float v0, float v1) {
    __half h0 = __float2half_rn(v0);
    __half h1 = __float2half_rn(v1);
    return ((uint32_t)__half_as_ushort(h1) << 16) | (uint32_t)__half_as_ushort(h0);
}
__device__ __forceinline__ float2 unpackh2(uint32_t u) {
    __half2 h = *(__half2*)&u;
    return __half22float2(h);
}
__device__ __forceinline__ void mma16816h(float* c, const uint32_t* a, const uint32_t* b) {
    asm volatile("mma.sync.aligned.m16n8k16.row.col.f32.f16.f16.f32 "
                 "{%0,%1,%2,%3}, {%4,%5,%6,%7}, {%8,%9}, {%0,%1,%2,%3};"
                 : "+f"(c[0]), "+f"(c[1]), "+f"(c[2]), "+f"(c[3])
                 : "r"(a[0]), "r"(a[1]), "r"(a[2]), "r"(a[3]), "r"(b[0]), "r"(b[1]));
}
__device__ __forceinline__ void cp16(uint32_t dst, const void* src) {
    asm volatile("cp.async.cg.shared.global [%0], [%1], 16;" :: "r"(dst), "l"(src));
}
__device__ __forceinline__ void red4(float* p, float a, float b, float c, float d) {
    asm volatile("red.global.add.v4.f32 [%0], {%1,%2,%3,%4};"
                 :: "l"(p), "f"(a), "f"(b), "f"(c), "f"(d) : "memory");
}

// ---------------- utility kernels ----------------
__global__ void zero4_kernel(float4* p, long long n4) {
    long long t = (long long)blockIdx.x * blockDim.x + threadIdx.x;
    if (t < n4) p[t] = make_float4(0.f, 0.f, 0.f, 0.f);
}
__global__ void init_bias_kernel(float* C, const float* __restrict__ bias, long long M, int N) {
    long long t = (long long)blockIdx.x * blockDim.x + threadIdx.x;
    if (t < M * N) C[t] = bias[t % N];
}

// ---------------- graph prep: counts -> scan -> scatter (CSR) ----------------
__global__ void count_kernel(const int* __restrict__ eidx, const int* __restrict__ etype) {
    int e = blockIdx.x * blockDim.x + threadIdx.x;
    if (e >= EE_) return;
    atomicAdd(&g_cnt[eidx[EE_ + e] * R_ + etype[e]], 1);
}
__global__ void scan_kernel() {
    __shared__ int part[1024];
    int tid = threadIdx.x;
    int base = tid * 40;
    int s = 0;
#pragma unroll 8
    for (int i = 0; i < 40; ++i) s += g_cnt[base + i];
    part[tid] = s;
    __syncthreads();
    for (int o = 1; o < 1024; o <<= 1) {
        int v = (tid >= o) ? part[tid - o] : 0;
        __syncthreads();
        part[tid] += v;
        __syncthreads();
    }
    int run = tid ? part[tid - 1] : 0;
#pragma unroll 8
    for (int i = 0; i < 40; ++i) {
        int c = g_cnt[base + i];
        g_off[base + i] = run;
        g_cur[base + i] = run;
        run += c;
    }
    if (tid == 1023) g_off[NR_] = run;
}
__global__ void scatter_kernel(const int* __restrict__ eidx, const int* __restrict__ etype) {
    int e = blockIdx.x * blockDim.x + threadIdx.x;
    if (e >= EE_) return;
    int pos = atomicAdd(&g_cur[eidx[EE_ + e] * R_ + etype[e]], 1);
    g_elist[pos] = eidx[e];
}

// x0 fp16 pack only; thread owns a column pair
__global__ void gather_mean_kernel(const float* __restrict__ tok, const int* __restrict__ wti) {
    long long t = (long long)blockIdx.x * blockDim.x + threadIdx.x;
    if (t >= (long long)NN_ * D2_) return;
    int n = (int)(t / D2_);
    int d = (int)(t % D2_) * 2;
    const int* w = wti + n * TPW_;
    float v0 = 0.f, v1 = 0.f;
#pragma unroll
    for (int i = 0; i < TPW_; ++i) {
        const float* r = tok + (size_t)w[i] * D_ + d;
        v0 += r[0]; v1 += r[1];
    }
    g_xh[t] = packh2(v0 * 0.25f, v1 * 0.25f);
}

// one CTA per dst node, 192 threads; thread owns 2 u32 (4 cols); fp16 in, fp32 acc, fp16 out.
__global__ void __launch_bounds__(192)
csr_agg_kernel(const uint32_t* __restrict__ xh) {
    int dst = blockIdx.x;
    int q = threadIdx.x * 2;      // u32 offset within row
#pragma unroll
    for (int r = 0; r < R_; ++r) {
        int beg = g_off[dst * R_ + r];
        int end = g_off[dst * R_ + r + 1];
        float4 a = make_float4(0.f, 0.f, 0.f, 0.f);
        for (int i = beg; i < end; ++i) {
            int src = g_elist[i];
            uint2 v = *(const uint2*)(xh + (size_t)src * D2_ + q);
            float2 f0 = unpackh2(v.x);
            float2 f1 = unpackh2(v.y);
            a.x += f0.x; a.y += f0.y; a.z += f1.x; a.w += f1.y;
        }
        float s = (end > beg) ? (1.f / (float)(end - beg)) : 0.f;
        size_t o = ((size_t)r * NN_ + dst) * D2_ + q;
        *(uint2*)&g_hh[o] = make_uint2(packh2(a.x * s, a.y * s), packh2(a.z * s, a.w * s));
    }
}

// Wcat(3840x768) -> k-pair packed fp16
__global__ void convertB_kernel(const float* __restrict__ Wrel, const float* __restrict__ Wroot) {
    int t = blockIdx.x * blockDim.x + threadIdx.x;
    if (t >= KP2_ * D_) return;
    int k2 = t / D_;
    int n  = t - k2 * D_;
    int k  = 2 * k2;
    const float* bp = (k < 4 * D_) ? (Wrel + (size_t)k * D_ + n)
                                   : (Wroot + (size_t)(k - 4 * D_) * D_ + n);
    g_bh[t] = packh2(bp[0], bp[D_]);
}

// ---------------- fp16 single-pass tensor GEMM: A + B both cp.async ----------------
// out = relu( [h0|h1|h2|h3|x](NN_ x 3840) @ Wcat + bias ); fp32 C and/or fp16 Yh.
#define GBM 128
#define GBN 256
#define GBK 32
#define NSTG (KTOT_ / GBK)   // 120
#define AP_  20              // A smem pitch u32 (16 k-pairs + 4 pad)
#define BP_  264             // B smem pitch u32 (256 + 8 pad)
#define ASZ_ (GBM * AP_)     // 2560 u32
#define BSZ_ (16 * BP_)      // 4224 u32
#define SBUF (ASZ_ + BSZ_)           // 6784 u32 per stage
#define GSMEM (2 * SBUF * 4)         // 54272 bytes

__global__ void __launch_bounds__(256, 1)
gemm_rgcn(const uint32_t* __restrict__ Hh, const uint32_t* __restrict__ Xh,
          const uint32_t* __restrict__ Bh,
          const float* __restrict__ bias, float* __restrict__ C,
          uint32_t* __restrict__ Yh) {
    extern __shared__ uint32_t sm[];
    const uint32_t sb = smem_u32(sm);
    const int tid  = threadIdx.x;
    const int wid  = tid >> 5;
    const int lane = tid & 31;
    const int g    = lane >> 2;
    const int tc   = lane & 3;
    const int wm   = wid & 3;        // 0..3 -> 32-row slice
    const int wn   = wid >> 2;       // 0..1 -> 128-col slice
    const int m0   = blockIdx.y * GBM;
    const int n0   = blockIdx.x * GBN;

    float acc[2][16][4];
#pragma unroll
    for (int i = 0; i < 2; ++i)
#pragma unroll
        for (int j = 0; j < 16; ++j)
#pragma unroll
            for (int q = 0; q < 4; ++q) acc[i][j][q] = 0.f;

    auto issueA = [&](int kc, int buf) {
        const int k0 = kc * GBK;
        const int r  = k0 / D_;
        const int dq = (k0 - r * D_) >> 1;
        const uint32_t* src = (r < 4) ? (Hh + ((size_t)r * NN_ + m0) * D2_ + dq)
                                      : (Xh + (size_t)m0 * D2_ + dq);
        const uint32_t aB = sb + (uint32_t)buf * (SBUF * 4);
#pragma unroll
        for (int i = 0; i < 2; ++i) {
            int c = tid + i * 256;
            int row = c >> 2, seg = c & 3;
            cp16(aB + row * (AP_ * 4) + seg * 16, src + (size_t)row * D2_ + seg * 4);
        }
    };
    auto issueB = [&](int kc, int buf) {
        const int kp0 = kc * 16;
        const uint32_t bbH = sb + (uint32_t)buf * (SBUF * 4) + ASZ_ * 4;
#pragma unroll
        for (int i = 0; i < 4; ++i) {
            int c = tid + i * 256;
            int row = c >> 6, seg = c & 63;
            size_t gidx = (size_t)(kp0 + row) * D_ + n0 + seg * 4;
            cp16(bbH + row * (BP_ * 4) + seg * 16, Bh + gidx);
        }
    };
    auto compute = [&](const uint32_t* s) {
        const uint32_t* AsH = s;
        const uint32_t* BsH = s + ASZ_;
#pragma unroll
        for (int ks = 0; ks < 2; ++ks) {
            const int kb = ks * 8;
            uint32_t aH[2][4];
#pragma unroll
            for (int mt = 0; mt < 2; ++mt) {
                int i0 = (wm * 32 + mt * 16 + g) * AP_ + kb + tc;
                int i1 = i0 + 8 * AP_;
                aH[mt][0] = AsH[i0]; aH[mt][1] = AsH[i1];
                aH[mt][2] = AsH[i0 + 4]; aH[mt][3] = AsH[i1 + 4];
            }
#pragma unroll
            for (int ng = 0; ng < 4; ++ng) {
                uint32_t bh[4][2];
#pragma unroll
                for (int q = 0; q < 4; ++q) {
                    int cb = wn * 128 + (ng * 4 + q) * 8;
                    int j0 = (kb + tc) * BP_ + cb + g;
                    int j1 = j0 + 4 * BP_;
                    bh[q][0] = BsH[j0]; bh[q][1] = BsH[j1];
                }
#pragma unroll
                for (int mt = 0; mt < 2; ++mt)
#pragma unroll
                    for (int q = 0; q < 4; ++q)
                        mma16816h(acc[mt][ng * 4 + q], aH[mt], bh[q]);
            }
        }
    };

    issueA(0, 0); issueB(0, 0);
    asm volatile("cp.async.commit_group;" ::: "memory");

#pragma unroll 1
    for (int kc = 0; kc < NSTG; ++kc) {
        const int cur = kc & 1;
        if (kc + 1 < NSTG) {
            issueA(kc + 1, 1 - cur);
            issueB(kc + 1, 1 - cur);
            asm volatile("cp.async.commit_group;" ::: "memory");
            asm volatile("cp.async.wait_group 1;" ::: "memory");
        } else {
            asm volatile("cp.async.wait_group 0;" ::: "memory");
        }
        __syncthreads();
        compute(sm + cur * SBUF);
        __syncthreads();
    }

    // ---- epilogue: bias + relu ----
#pragma unroll
    for (int mt = 0; mt < 2; ++mt) {
        int row = m0 + wm * 32 + mt * 16 + g;
#pragma unroll
        for (int nt = 0; nt < 16; ++nt) {
            int col = n0 + wn * 128 + nt * 8 + tc * 2;
            float b0 = __ldg(bias + col);
            float b1 = __ldg(bias + col + 1);
            float2 v0 = make_float2(fmaxf(acc[mt][nt][0] + b0, 0.f),
                                    fmaxf(acc[mt][nt][1] + b1, 0.f));
            float2 v1 = make_float2(fmaxf(acc[mt][nt][2] + b0, 0.f),
                                    fmaxf(acc[mt][nt][3] + b1, 0.f));
            if (C) {
                *(float2*)(C + (size_t)row * D_ + col)       = v0;
                *(float2*)(C + (size_t)(row + 8) * D_ + col) = v1;
            }
            if (Yh) {
                Yh[(size_t)row * D2_ + (col >> 1)]       = packh2(v0.x, v0.y);
                Yh[(size_t)(row + 8) * D2_ + (col >> 1)] = packh2(v1.x, v1.y);
            }
        }
    }
}

// ---------------- split-K fp32 GEMM for head ops: C += A(MxK)@B(KxN) over k-chunk ----------------
#define HB 64
#define HK 16
__global__ void __launch_bounds__(256)
sgemm_splitk(const float* __restrict__ A, const float* __restrict__ Bm,
             float* __restrict__ C, int M, int N, int K, int kchunk) {
    __shared__ float As[HK][HB + 4];
    __shared__ float Bs[HK][HB + 4];
    const int tid = threadIdx.x;
    const int tr = tid >> 4;
    const int tcol = tid & 15;
    const int m0 = blockIdx.y * HB;
    const int n0 = blockIdx.x * HB;
    const int k0 = blockIdx.z * kchunk;
    const int ar = tid >> 2, ac = (tid & 3) * 4;
    const int br = tid >> 4, bc = (tid & 15) * 4;
    float acc[4][4] = {};
    for (int kk = 0; kk < kchunk; kk += HK) {
        int k = k0 + kk;
        float4 av = (m0 + ar < M) ? *(const float4*)(A + (size_t)(m0 + ar) * K + k + ac)
                                  : make_float4(0.f, 0.f, 0.f, 0.f);
        As[ac + 0][ar] = av.x;
        As[ac + 1][ar] = av.y;
        As[ac + 2][ar] = av.z;
        As[ac + 3][ar] = av.w;
        *(float4*)&Bs[br][bc] = *(const float4*)(Bm + (size_t)(k + br) * N + n0 + bc);
        __syncthreads();
#pragma unroll
        for (int kq = 0; kq < HK; ++kq) {
            float rm[4], rn[4];
#pragma unroll
            for (int i = 0; i < 4; ++i) rm[i] = As[kq][tr * 4 + i];
#pragma unroll
            for (int j = 0; j < 4; ++j) rn[j] = Bs[kq][tcol * 4 + j];
#pragma unroll
            for (int i = 0; i < 4; ++i)
#pragma unroll
                for (int j = 0; j < 4; ++j)
                    acc[i][j] += rm[i] * rn[j];
        }
        __syncthreads();
    }
#pragma unroll
    for (int i = 0; i < 4; ++i) {
        int row = m0 + tr * 4 + i;
        if (row < M)
            red4(C + (size_t)row * N + n0 + tcol * 4,
                 acc[i][0], acc[i][1], acc[i][2], acc[i][3]);
    }
}

// ---------------- head kernels ----------------
__global__ void ev_pool_kernel() {
    int t = blockIdx.x * blockDim.x + threadIdx.x;
    if (t >= SEQS_ * DOUT_) return;
    int s = t / DOUT_, d = t % DOUT_;
    const float* base = g_x + (size_t)s * WORDS_ * DOUT_ + d;
    float sum = 0.f, mx = -1e30f;
#pragma unroll 8
    for (int w = 0; w < WORDS_; ++w) {
        float v = base[(size_t)w * DOUT_];
        sum += v;
        mx = fmaxf(mx, v);
    }
    g_ev[s * (2 * DOUT_) + d]         = sum * (1.f / WORDS_);
    g_ev[s * (2 * DOUT_) + DOUT_ + d] = mx;
}
__global__ void build_attin_kernel(const float* __restrict__ tok, const int* __restrict__ csi) {
    int t = blockIdx.x * blockDim.x + threadIdx.x;
    const int W = D_ + 2 * DOUT_;
    if (t >= SEQS_ * W) return;
    int s = t / W, c = t % W;
    if (c < D_) {
        int seq = csi[s / EVI_];
        g_attin[t] = tok[(size_t)seq * L_ * D_ + c];
    } else {
        g_attin[t] = g_ev[s * (2 * DOUT_) + (c - D_)];
    }
}
__global__ void dotp_kernel(const float* __restrict__ att_w1) {
    int s = blockIdx.x;
    int tid = threadIdx.x;
    float acc = 0.f;
    for (int k = tid; k < DOUT_; k += 256) {
        float h = g_hatt[(size_t)s * DOUT_ + k];
        acc += fmaxf(h, 0.f) * att_w1[k];
    }
#pragma unroll
    for (int o = 16; o; o >>= 1) acc += __shfl_down_sync(0xffffffffu, acc, o);
    __shared__ float sw[8];
    if ((tid & 31) == 0) sw[tid >> 5] = acc;
    __syncthreads();
    if (tid == 0) {
        float r = 0.f;
#pragma unroll
        for (int w = 0; w < 8; ++w) r += sw[w];
        g_p[s] = r;
    }
}
__global__ void softmax_att_kernel(float* __restrict__ out) {
    int b = blockIdx.x;
    if (threadIdx.x != 0) return;
    float pv[EVI_];
    float m = -1e30f;
#pragma unroll
    for (int e = 0; e < EVI_; ++e) { pv[e] = g_p[b * EVI_ + e]; m = fmaxf(m, pv[e]); }
    float s = 0.f;
#pragma unroll
    for (int e = 0; e < EVI_; ++e) { pv[e] = expf(pv[e] - m); s += pv[e]; }
    float is = 1.f / s;
#pragma unroll
    for (int e = 0; e < EVI_; ++e) {
        g_a[b * EVI_ + e] = pv[e] * is;
        float p = g_p[b * EVI_ + e];
        out[B_ * NC_ + b * EVI_ + e] = 1.f / (1.f + expf(-p));
    }
}
__global__ void graph_rep_kernel(const float* __restrict__ concat_cls) {
    int t = blockIdx.x * blockDim.x + threadIdx.x;
    const int W = 2 * DOUT_ + D_;
    if (t >= B_ * W) return;
    int b = t / W, c = t % W;
    if (c < 2 * DOUT_) {
        float acc = 0.f;
#pragma unroll
        for (int e = 0; e < EVI_; ++e)
            acc += g_a[b * EVI_ + e] * g_ev[(size_t)(b * EVI_ + e) * (2 * DOUT_) + c];
        g_rep[t] = acc;
    } else {
        g_rep[t] = concat_cls[b * D_ + (c - 2 * DOUT_)];
    }
}
__global__ void final_kernel(const float* __restrict__ lin2_w,
                             const float* __restrict__ lin2_b,
                             float* __restrict__ out) {
    int b = blockIdx.x;
    int tid = threadIdx.x;
    float a0 = 0.f, a1 = 0.f, a2 = 0.f;
    for (int k = tid; k < LH_; k += 128) {
        float h = fmaxf(g_hid[(size_t)b * LH_ + k], 0.f);
        a0 += h * lin2_w[k * NC_ + 0];
        a1 += h * lin2_w[k * NC_ + 1];
        a2 += h * lin2_w[k * NC_ + 2];
    }
#pragma unroll
    for (int o = 16; o; o >>= 1) {
        a0 += __shfl_down_sync(0xffffffffu, a0, o);
        a1 += __shfl_down_sync(0xffffffffu, a1, o);
        a2 += __shfl_down_sync(0xffffffffu, a2, o);
    }
    __shared__ float s0[4], s1[4], s2[4];
    if ((tid & 31) == 0) { int w = tid >> 5; s0[w] = a0; s1[w] = a1; s2[w] = a2; }
    __syncthreads();
    if (tid == 0) {
        float l0 = s0[0] + s0[1] + s0[2] + s0[3] + lin2_b[0];
        float l1 = s1[0] + s1[1] + s1[2] + s1[3] + lin2_b[1];
        float l2 = s2[0] + s2[1] + s2[2] + s2[3] + lin2_b[2];
        float m = fmaxf(l0, fmaxf(l1, l2));
        float lse = logf(expf(l0 - m) + expf(l1 - m) + expf(l2 - m)) + m;
        out[b * NC_ + 0] = l0 - lse;
        out[b * NC_ + 1] = l1 - lse;
        out[b * NC_ + 2] = l2 - lse;
    }
}

// ---------------- launch ----------------
extern "C" void kernel_launch(void* const* d_in, const int* in_sizes, int n_in,
                              void* d_out, int out_size) {
    const float* token_feats = (const float*)d_in[0];
    const float* concat_cls  = (const float*)d_in[1];
    const float* W_rel1      = (const float*)d_in[2];
    const float* W_root1     = (const float*)d_in[3];
    const float* b1          = (const float*)d_in[4];
    const float* W_rel2      = (const float*)d_in[5];
    const float* W_root2     = (const float*)d_in[6];
    const float* b2          = (const float*)d_in[7];
    const float* att_w0      = (const float*)d_in[8];
    const float* att_w1      = (const float*)d_in[9];
    const float* lin1_w      = (const float*)d_in[10];
    const float* lin1_b      = (const float*)d_in[11];
    const float* lin2_w      = (const float*)d_in[12];
    const float* lin2_b      = (const float*)d_in[13];
    const int*   wti         = (const int*)d_in[14];
    const int*   eidx        = (const int*)d_in[15];
    const int*   etype       = (const int*)d_in[16];
    const int*   csi         = (const int*)d_in[17];
    float* out = (float*)d_out;

    float *p_x, *p_attin, *p_hatt, *p_rep, *p_hid;
    int* p_cnt;
    uint32_t *p_hh, *p_xh, *p_yh, *p_bh;
    cudaGetSymbolAddress((void**)&p_x,     g_x);
    cudaGetSymbolAddress((void**)&p_cnt,   g_cnt);
    cudaGetSymbolAddress((void**)&p_attin, g_attin);
    cudaGetSymbolAddress((void**)&p_hatt,  g_hatt);
    cudaGetSymbolAddress((void**)&p_rep,   g_rep);
    cudaGetSymbolAddress((void**)&p_hid,   g_hid);
    cudaGetSymbolAddress((void**)&p_hh,    g_hh);
    cudaGetSymbolAddress((void**)&p_xh,    g_xh);
    cudaGetSymbolAddress((void**)&p_yh,    g_yh);
    cudaGetSymbolAddress((void**)&p_bh,    g_bh);

    cudaFuncSetAttribute(gemm_rgcn, cudaFuncAttributeMaxDynamicSharedMemorySize, GSMEM);

    const int T = 256;
    const long long NQ = (long long)NN_ * D2_;
    const int CVB = KP2_ * D_;
    const dim3 ggrid(D_ / GBN, NN_ / GBM);   // (3, 80)
    const int HKW = D_ + 2 * DOUT_;          // 2304

    // --- graph prep: CSR ---
    zero4_kernel<<<(NR_ / 4 + T - 1) / T, T>>>((float4*)p_cnt, NR_ / 4);
    count_kernel<<<(EE_ + T - 1) / T, T>>>(eidx, etype);
    scan_kernel<<<1, 1024>>>();
    scatter_kernel<<<(EE_ + T - 1) / T, T>>>(eidx, etype);

    // --- x0 (fp16 only) ---
    gather_mean_kernel<<<(unsigned)((NQ + T - 1) / T), T>>>(token_feats, wti);

    // --- layer 1 (fp16 in, fp16 out only) ---
    csr_agg_kernel<<<NN_, 192>>>(p_xh);
    convertB_kernel<<<(CVB + T - 1) / T, T>>>(W_rel1, W_root1);
    gemm_rgcn<<<ggrid, 256, GSMEM>>>(p_hh, p_xh, p_bh, b1, nullptr, p_yh);

    // --- layer 2 (fp16 in, fp32 out for head) ---
    csr_agg_kernel<<<NN_, 192>>>(p_yh);
    convertB_kernel<<<(CVB + T - 1) / T, T>>>(W_rel2, W_root2);
    gemm_rgcn<<<ggrid, 256, GSMEM>>>(p_hh, p_yh, p_bh, b2, p_x, nullptr);

    // --- evidence pooling + attention ---
    ev_pool_kernel<<<(SEQS_ * DOUT_ + T - 1) / T, T>>>();
    build_attin_kernel<<<(SEQS_ * HKW + T - 1) / T, T>>>(token_feats, csi);
    zero4_kernel<<<(SEQS_ * DOUT_ / 4 + T - 1) / T, T>>>((float4*)p_hatt, SEQS_ * DOUT_ / 4);
    {
        dim3 hg(DOUT_ / HB, (SEQS_ + HB - 1) / HB, 8);   // (12, 5, 8)
        sgemm_splitk<<<hg, 256>>>(p_attin, att_w0, p_hatt, SEQS_, DOUT_, HKW, HKW / 8);
    }
    dotp_kernel<<<SEQS_, 256>>>(att_w1);
    softmax_att_kernel<<<B_, 32>>>(out);

    // --- graph readout + classifier ---
    graph_rep_kernel<<<(B_ * HKW + T - 1) / T, T>>>(concat_cls);
    init_bias_kernel<<<(B_ * LH_ + T - 1) / T, T>>>(p_hid, lin1_b, B_, LH_);
    {
        dim3 hg(LH_ / HB, (B_ + HB - 1) / HB, 8);        // (16, 1, 8)
        sgemm_splitk<<<hg, 256>>>(p_rep, lin1_w, p_hid, B_, LH_, HKW, HKW / 8);
    }
    final_kernel<<<B_, 128>>>(lin2_w, lin2_b, out);
}

// round 12
// speedup vs baseline: 3.0817x; 1.0182x over previous
#include <cuda_runtime.h>
#include <cuda_fp16.h>
#include <math.h>
#include <stdint.h>

// ---------------- problem constants ----------------
#define B_      64
#define EVI_    5
#define SEQS_   (B_ * EVI_)          // 320
#define L_      256
#define D_      768
#define D2_     (D_ / 2)             // 384 u32 per fp16-pair row
#define WORDS_  32
#define TPW_    4
#define NN_     (SEQS_ * WORDS_)     // 10240 nodes
#define EE_     (NN_ * 16)           // 163840 edges
#define R_      4
#define DOUT_   768
#define LH_     1024
#define NC_     3
#define KTOT_   (5 * D_)             // 3840 fused K
#define NR_     (NN_ * R_)           // 40960 segments
#define KP2_    (KTOT_ / 2)          // 1920 k-pairs

// ---------------- scratch (device globals; no allocs allowed) ----------------
__device__ uint32_t g_hh  [(size_t)R_ * NN_ * D2_];  // fp16 h, k-pair packed
__device__ uint32_t g_xh  [(size_t)NN_ * D2_];       // fp16 x0
__device__ uint32_t g_yh  [(size_t)NN_ * D2_];       // fp16 x1
__device__ uint32_t g_bh1 [(size_t)KP2_ * D_];       // fp16 Wcat layer 1
__device__ uint32_t g_bh2 [(size_t)KP2_ * D_];       // fp16 Wcat layer 2
__device__ int      g_cnt [NR_];
__device__ int      g_off [NR_ + 1];
__device__ int      g_cur [NR_];
__device__ int      g_elist[EE_];
__device__ float    g_ev  [SEQS_ * 2 * DOUT_];
__device__ float    g_attin[SEQS_ * (D_ + 2 * DOUT_)];
__device__ float    g_hatt[SEQS_ * DOUT_];
__device__ float    g_a   [SEQS_];
__device__ float    g_rep [B_ * (2 * DOUT_ + D_)];
__device__ float    g_hid [B_ * LH_];

// ---------------- small device helpers ----------------
__device__ __forceinline__ uint32_t smem_u32(const void* p) {
    uint32_t a;
    asm("{ .reg .u64 t; cvta.to.shared.u64 t, %1; cvt.u32.u64 %0, t; }" : "=r"(a) : "l"(p));
    return a;
}
__device__ __forceinline__ uint32_t packh2(float v0, float v1) {
    __half h0 = __float2half_rn(v0);
    __half h1 = __float2half_rn(v1);
    return ((uint32_t)__half_as_ushort(h1) << 16) | (uint32_t)__half_as_ushort(h0);
}
__device__ __forceinline__ float2 unpackh2(uint32_t u) {
    __half2 h = *(__half2*)&u;
    return __half22float2(h);
}
__device__ __forceinline__ void mma16816h(float* c, const uint32_t* a, const uint32_t* b) {
    asm volatile("mma.sync.aligned.m16n8k16.row.col.f32.f16.f16.f32 "
                 "{%0,%1,%2,%3}, {%4,%5,%6,%7}, {%8,%9}, {%0,%1,%2,%3};"
                 : "+f"(c[0]), "+f"(c[1]), "+f"(c[2]), "+f"(c[3])
                 : "r"(a[0]), "r"(a[1]), "r"(a[2]), "r"(a[3]), "r"(b[0]), "r"(b[1]));
}
__device__ __forceinline__ void cp16(uint32_t dst, const void* src) {
    asm volatile("cp.async.cg.shared.global [%0], [%1], 16;" :: "r"(dst), "l"(src));
}
__device__ __forceinline__ void red4(float* p, float a, float b, float c, float d) {
    asm volatile("red.global.add.v4.f32 [%0], {%1,%2,%3,%4};"
                 :: "l"(p), "f"(a), "f"(b), "f"(c), "f"(d) : "memory");
}

// ---------------- utility kernels ----------------
__global__ void zero4_kernel(float4* p, long long n4) {
    long long t = (long long)blockIdx.x * blockDim.x + threadIdx.x;
    if (t < n4) p[t] = make_float4(0.f, 0.f, 0.f, 0.f);
}

// ---------------- graph prep: counts -> scan -> scatter (CSR) ----------------
__global__ void count_kernel(const int* __restrict__ eidx, const int* __restrict__ etype) {
    int e = blockIdx.x * blockDim.x + threadIdx.x;
    if (e >= EE_) return;
    atomicAdd(&g_cnt[eidx[EE_ + e] * R_ + etype[e]], 1);
}
__global__ void scan_kernel() {
    __shared__ int part[1024];
    int tid = threadIdx.x;
    int base = tid * 40;
    int s = 0;
#pragma unroll 8
    for (int i = 0; i < 40; ++i) s += g_cnt[base + i];
    part[tid] = s;
    __syncthreads();
    for (int o = 1; o < 1024; o <<= 1) {
        int v = (tid >= o) ? part[tid - o] : 0;
        __syncthreads();
        part[tid] += v;
        __syncthreads();
    }
    int run = tid ? part[tid - 1] : 0;
#pragma unroll 8
    for (int i = 0; i < 40; ++i) {
        int c = g_cnt[base + i];
        g_off[base + i] = run;
        g_cur[base + i] = run;
        run += c;
    }
    if (tid == 1023) g_off[NR_] = run;
}
__global__ void scatter_kernel(const int* __restrict__ eidx, const int* __restrict__ etype) {
    int e = blockIdx.x * blockDim.x + threadIdx.x;
    if (e >= EE_) return;
    int pos = atomicAdd(&g_cur[eidx[EE_ + e] * R_ + etype[e]], 1);
    g_elist[pos] = eidx[e];
}

// x0 fp16 pack; thread owns a column pair
__global__ void gather_mean_kernel(const float* __restrict__ tok, const int* __restrict__ wti) {
    long long t = (long long)blockIdx.x * blockDim.x + threadIdx.x;
    if (t >= (long long)NN_ * D2_) return;
    int n = (int)(t / D2_);
    int d = (int)(t % D2_) * 2;
    const int* w = wti + n * TPW_;
    float v0 = 0.f, v1 = 0.f;
#pragma unroll
    for (int i = 0; i < TPW_; ++i) {
        const float* r = tok + (size_t)w[i] * D_ + d;
        v0 += r[0]; v1 += r[1];
    }
    g_xh[t] = packh2(v0 * 0.25f, v1 * 0.25f);
}

// one CTA per dst node, 192 threads; fp16 in, fp32 acc, fp16 out.
__global__ void __launch_bounds__(192)
csr_agg_kernel(const uint32_t* __restrict__ xh) {
    int dst = blockIdx.x;
    int q = threadIdx.x * 2;
#pragma unroll
    for (int r = 0; r < R_; ++r) {
        int beg = g_off[dst * R_ + r];
        int end = g_off[dst * R_ + r + 1];
        float4 a = make_float4(0.f, 0.f, 0.f, 0.f);
        for (int i = beg; i < end; ++i) {
            int src = g_elist[i];
            uint2 v = *(const uint2*)(xh + (size_t)src * D2_ + q);
            float2 f0 = unpackh2(v.x);
            float2 f1 = unpackh2(v.y);
            a.x += f0.x; a.y += f0.y; a.z += f1.x; a.w += f1.y;
        }
        float s = (end > beg) ? (1.f / (float)(end - beg)) : 0.f;
        size_t o = ((size_t)r * NN_ + dst) * D2_ + q;
        *(uint2*)&g_hh[o] = make_uint2(packh2(a.x * s, a.y * s), packh2(a.z * s, a.w * s));
    }
}

// both layers' Wcat -> fp16 k-pair packed
__global__ void convertB_both_kernel(const float* __restrict__ Wrel1, const float* __restrict__ Wroot1,
                                     const float* __restrict__ Wrel2, const float* __restrict__ Wroot2) {
    int t = blockIdx.x * blockDim.x + threadIdx.x;
    if (t >= KP2_ * D_) return;
    int k2 = t / D_;
    int n  = t - k2 * D_;
    int k  = 2 * k2;
    if (k < 4 * D_) {
        const float* b1 = Wrel1 + (size_t)k * D_ + n;
        const float* b2 = Wrel2 + (size_t)k * D_ + n;
        g_bh1[t] = packh2(b1[0], b1[D_]);
        g_bh2[t] = packh2(b2[0], b2[D_]);
    } else {
        const float* b1 = Wroot1 + (size_t)(k - 4 * D_) * D_ + n;
        const float* b2 = Wroot2 + (size_t)(k - 4 * D_) * D_ + n;
        g_bh1[t] = packh2(b1[0], b1[D_]);
        g_bh2[t] = packh2(b2[0], b2[D_]);
    }
}

// ---------------- fp16 single-pass tensor GEMM: A + B both cp.async ----------------
// relu( [h0|h1|h2|h3|x] @ Wcat + bias ) -> fp16 Yh, or pooled mean|max -> Ev
#define GBM 128
#define GBN 256
#define GBK 32
#define NSTG (KTOT_ / GBK)   // 120
#define AP_  20
#define BP_  264
#define ASZ_ (GBM * AP_)     // 2560 u32
#define BSZ_ (16 * BP_)      // 4224 u32
#define SBUF (ASZ_ + BSZ_)
#define GSMEM (2 * SBUF * 4)

__global__ void __launch_bounds__(256, 1)
gemm_rgcn(const uint32_t* __restrict__ Hh, const uint32_t* __restrict__ Xh,
          const uint32_t* __restrict__ Bh,
          const float* __restrict__ bias,
          uint32_t* __restrict__ Yh, float* __restrict__ Ev) {
    extern __shared__ uint32_t sm[];
    const uint32_t sb = smem_u32(sm);
    const int tid  = threadIdx.x;
    const int wid  = tid >> 5;
    const int lane = tid & 31;
    const int g    = lane >> 2;
    const int tc   = lane & 3;
    const int wm   = wid & 3;        // 0..3 -> 32-row slice (one sequence)
    const int wn   = wid >> 2;       // 0..1 -> 128-col slice
    const int m0   = blockIdx.y * GBM;
    const int n0   = blockIdx.x * GBN;

    float acc[2][16][4];
#pragma unroll
    for (int i = 0; i < 2; ++i)
#pragma unroll
        for (int j = 0; j < 16; ++j)
#pragma unroll
            for (int q = 0; q < 4; ++q) acc[i][j][q] = 0.f;

    auto issueA = [&](int kc, int buf) {
        const int k0 = kc * GBK;
        const int r  = k0 / D_;
        const int dq = (k0 - r * D_) >> 1;
        const uint32_t* src = (r < 4) ? (Hh + ((size_t)r * NN_ + m0) * D2_ + dq)
                                      : (Xh + (size_t)m0 * D2_ + dq);
        const uint32_t aB = sb + (uint32_t)buf * (SBUF * 4);
#pragma unroll
        for (int i = 0; i < 2; ++i) {
            int c = tid + i * 256;
            int row = c >> 2, seg = c & 3;
            cp16(aB + row * (AP_ * 4) + seg * 16, src + (size_t)row * D2_ + seg * 4);
        }
    };
    auto issueB = [&](int kc, int buf) {
        const int kp0 = kc * 16;
        const uint32_t bbH = sb + (uint32_t)buf * (SBUF * 4) + ASZ_ * 4;
#pragma unroll
        for (int i = 0; i < 4; ++i) {
            int c = tid + i * 256;
            int row = c >> 6, seg = c & 63;
            size_t gidx = (size_t)(kp0 + row) * D_ + n0 + seg * 4;
            cp16(bbH + row * (BP_ * 4) + seg * 16, Bh + gidx);
        }
    };
    auto compute = [&](const uint32_t* s) {
        const uint32_t* AsH = s;
        const uint32_t* BsH = s + ASZ_;
#pragma unroll
        for (int ks = 0; ks < 2; ++ks) {
            const int kb = ks * 8;
            uint32_t aH[2][4];
#pragma unroll
            for (int mt = 0; mt < 2; ++mt) {
                int i0 = (wm * 32 + mt * 16 + g) * AP_ + kb + tc;
                int i1 = i0 + 8 * AP_;
                aH[mt][0] = AsH[i0]; aH[mt][1] = AsH[i1];
                aH[mt][2] = AsH[i0 + 4]; aH[mt][3] = AsH[i1 + 4];
            }
#pragma unroll
            for (int ng = 0; ng < 4; ++ng) {
                uint32_t bh[4][2];
#pragma unroll
                for (int q = 0; q < 4; ++q) {
                    int cb = wn * 128 + (ng * 4 + q) * 8;
                    int j0 = (kb + tc) * BP_ + cb + g;
                    int j1 = j0 + 4 * BP_;
                    bh[q][0] = BsH[j0]; bh[q][1] = BsH[j1];
                }
#pragma unroll
                for (int mt = 0; mt < 2; ++mt)
#pragma unroll
                    for (int q = 0; q < 4; ++q)
                        mma16816h(acc[mt][ng * 4 + q], aH[mt], bh[q]);
            }
        }
    };

    issueA(0, 0); issueB(0, 0);
    asm volatile("cp.async.commit_group;" ::: "memory");

#pragma unroll 1
    for (int kc = 0; kc < NSTG; ++kc) {
        const int cur = kc & 1;
        if (kc + 1 < NSTG) {
            issueA(kc + 1, 1 - cur);
            issueB(kc + 1, 1 - cur);
            asm volatile("cp.async.commit_group;" ::: "memory");
            asm volatile("cp.async.wait_group 1;" ::: "memory");
        } else {
            asm volatile("cp.async.wait_group 0;" ::: "memory");
        }
        __syncthreads();
        compute(sm + cur * SBUF);
        __syncthreads();
    }

    if (Ev) {
        // ---- pooled epilogue: bias+relu, then mean/max over the 32 words (this warp's rows) ----
        const int seq = blockIdx.y * 4 + wm;
#pragma unroll
        for (int nt = 0; nt < 16; ++nt) {
            int col = n0 + wn * 128 + nt * 8 + tc * 2;
            float b0 = __ldg(bias + col);
            float b1 = __ldg(bias + col + 1);
            float s0 = 0.f, s1 = 0.f, x0 = 0.f, x1 = 0.f;
#pragma unroll
            for (int mt = 0; mt < 2; ++mt) {
                float v;
                v = fmaxf(acc[mt][nt][0] + b0, 0.f); s0 += v; x0 = fmaxf(x0, v);
                v = fmaxf(acc[mt][nt][2] + b0, 0.f); s0 += v; x0 = fmaxf(x0, v);
                v = fmaxf(acc[mt][nt][1] + b1, 0.f); s1 += v; x1 = fmaxf(x1, v);
                v = fmaxf(acc[mt][nt][3] + b1, 0.f); s1 += v; x1 = fmaxf(x1, v);
            }
#pragma unroll
            for (int off = 4; off <= 16; off <<= 1) {
                s0 += __shfl_xor_sync(0xffffffffu, s0, off);
                s1 += __shfl_xor_sync(0xffffffffu, s1, off);
                x0 = fmaxf(x0, __shfl_xor_sync(0xffffffffu, x0, off));
                x1 = fmaxf(x1, __shfl_xor_sync(0xffffffffu, x1, off));
            }
            if (lane < 4) {
                float* evr = Ev + (size_t)seq * (2 * DOUT_);
                evr[col]            = s0 * (1.f / WORDS_);
                evr[col + 1]        = s1 * (1.f / WORDS_);
                evr[DOUT_ + col]    = x0;
                evr[DOUT_ + col + 1] = x1;
            }
        }
    } else {
        // ---- standard epilogue: bias + relu -> fp16 ----
#pragma unroll
        for (int mt = 0; mt < 2; ++mt) {
            int row = m0 + wm * 32 + mt * 16 + g;
#pragma unroll
            for (int nt = 0; nt < 16; ++nt) {
                int col = n0 + wn * 128 + nt * 8 + tc * 2;
                float b0 = __ldg(bias + col);
                float b1 = __ldg(bias + col + 1);
                float2 v0 = make_float2(fmaxf(acc[mt][nt][0] + b0, 0.f),
                                        fmaxf(acc[mt][nt][1] + b1, 0.f));
                float2 v1 = make_float2(fmaxf(acc[mt][nt][2] + b0, 0.f),
                                        fmaxf(acc[mt][nt][3] + b1, 0.f));
                Yh[(size_t)row * D2_ + (col >> 1)]       = packh2(v0.x, v0.y);
                Yh[(size_t)(row + 8) * D2_ + (col >> 1)] = packh2(v1.x, v1.y);
            }
        }
    }
}

// ---------------- split-K fp32 GEMM for head ops ----------------
#define HB 64
#define HK 16
__global__ void __launch_bounds__(256)
sgemm_splitk(const float* __restrict__ A, const float* __restrict__ Bm,
             float* __restrict__ C, int M, int N, int K, int kchunk) {
    __shared__ float As[HK][HB + 4];
    __shared__ float Bs[HK][HB + 4];
    const int tid = threadIdx.x;
    const int tr = tid >> 4;
    const int tcol = tid & 15;
    const int m0 = blockIdx.y * HB;
    const int n0 = blockIdx.x * HB;
    const int k0 = blockIdx.z * kchunk;
    const int ar = tid >> 2, ac = (tid & 3) * 4;
    const int br = tid >> 4, bc = (tid & 15) * 4;
    float acc[4][4] = {};
    for (int kk = 0; kk < kchunk; kk += HK) {
        int k = k0 + kk;
        float4 av = (m0 + ar < M) ? *(const float4*)(A + (size_t)(m0 + ar) * K + k + ac)
                                  : make_float4(0.f, 0.f, 0.f, 0.f);
        As[ac + 0][ar] = av.x;
        As[ac + 1][ar] = av.y;
        As[ac + 2][ar] = av.z;
        As[ac + 3][ar] = av.w;
        *(float4*)&Bs[br][bc] = *(const float4*)(Bm + (size_t)(k + br) * N + n0 + bc);
        __syncthreads();
#pragma unroll
        for (int kq = 0; kq < HK; ++kq) {
            float rm[4], rn[4];
#pragma unroll
            for (int i = 0; i < 4; ++i) rm[i] = As[kq][tr * 4 + i];
#pragma unroll
            for (int j = 0; j < 4; ++j) rn[j] = Bs[kq][tcol * 4 + j];
#pragma unroll
            for (int i = 0; i < 4; ++i)
#pragma unroll
                for (int j = 0; j < 4; ++j)
                    acc[i][j] += rm[i] * rn[j];
        }
        __syncthreads();
    }
#pragma unroll
    for (int i = 0; i < 4; ++i) {
        int row = m0 + tr * 4 + i;
        if (row < M)
            red4(C + (size_t)row * N + n0 + tcol * 4,
                 acc[i][0], acc[i][1], acc[i][2], acc[i][3]);
    }
}

// ---------------- fused head kernels ----------------
// attin build + hatt zero
__global__ void attin_prep_kernel(const float* __restrict__ tok, const int* __restrict__ csi) {
    int t = blockIdx.x * blockDim.x + threadIdx.x;
    const int W = D_ + 2 * DOUT_;
    const int NA = SEQS_ * W;
    if (t < NA) {
        int s = t / W, c = t % W;
        if (c < D_) {
            int seq = csi[s / EVI_];
            g_attin[t] = tok[(size_t)seq * L_ * D_ + c];
        } else {
            g_attin[t] = g_ev[s * (2 * DOUT_) + (c - D_)];
        }
    } else {
        int u = t - NA;
        if (u < SEQS_ * DOUT_) g_hatt[u] = 0.f;
    }
}
// per-batch: 5 dot products + softmax + sigmoid out
__global__ void dotp_softmax_kernel(const float* __restrict__ att_w1, float* __restrict__ out) {
    int b = blockIdx.x;
    int tid = threadIdx.x;
    __shared__ float red[8];
    __shared__ float pv[EVI_];
#pragma unroll
    for (int e = 0; e < EVI_; ++e) {
        int s = b * EVI_ + e;
        float acc = 0.f;
        for (int k = tid; k < DOUT_; k += 256)
            acc += fmaxf(g_hatt[(size_t)s * DOUT_ + k], 0.f) * att_w1[k];
#pragma unroll
        for (int o = 16; o; o >>= 1) acc += __shfl_down_sync(0xffffffffu, acc, o);
        if ((tid & 31) == 0) red[tid >> 5] = acc;
        __syncthreads();
        if (tid == 0) {
            float r = 0.f;
#pragma unroll
            for (int w = 0; w < 8; ++w) r += red[w];
            pv[e] = r;
        }
        __syncthreads();
    }
    if (tid == 0) {
        float m = -1e30f;
#pragma unroll
        for (int e = 0; e < EVI_; ++e) m = fmaxf(m, pv[e]);
        float s = 0.f;
        float ex[EVI_];
#pragma unroll
        for (int e = 0; e < EVI_; ++e) { ex[e] = expf(pv[e] - m); s += ex[e]; }
        float is = 1.f / s;
#pragma unroll
        for (int e = 0; e < EVI_; ++e) {
            g_a[b * EVI_ + e] = ex[e] * is;
            out[B_ * NC_ + b * EVI_ + e] = 1.f / (1.f + expf(-pv[e]));
        }
    }
}
// graph readout + lin1 bias init
__global__ void rep_bias_kernel(const float* __restrict__ concat_cls, const float* __restrict__ lin1_b) {
    int t = blockIdx.x * blockDim.x + threadIdx.x;
    const int W = 2 * DOUT_ + D_;
    const int NR = B_ * W;
    if (t < NR) {
        int b = t / W, c = t % W;
        if (c < 2 * DOUT_) {
            float acc = 0.f;
#pragma unroll
            for (int e = 0; e < EVI_; ++e)
                acc += g_a[b * EVI_ + e] * g_ev[(size_t)(b * EVI_ + e) * (2 * DOUT_) + c];
            g_rep[t] = acc;
        } else {
            g_rep[t] = concat_cls[b * D_ + (c - 2 * DOUT_)];
        }
    } else {
        int u = t - NR;
        if (u < B_ * LH_) g_hid[u] = lin1_b[u % LH_];
    }
}
__global__ void final_kernel(const float* __restrict__ lin2_w,
                             const float* __restrict__ lin2_b,
                             float* __restrict__ out) {
    int b = blockIdx.x;
    int tid = threadIdx.x;
    float a0 = 0.f, a1 = 0.f, a2 = 0.f;
    for (int k = tid; k < LH_; k += 128) {
        float h = fmaxf(g_hid[(size_t)b * LH_ + k], 0.f);
        a0 += h * lin2_w[k * NC_ + 0];
        a1 += h * lin2_w[k * NC_ + 1];
        a2 += h * lin2_w[k * NC_ + 2];
    }
#pragma unroll
    for (int o = 16; o; o >>= 1) {
        a0 += __shfl_down_sync(0xffffffffu, a0, o);
        a1 += __shfl_down_sync(0xffffffffu, a1, o);
        a2 += __shfl_down_sync(0xffffffffu, a2, o);
    }
    __shared__ float s0[4], s1[4], s2[4];
    if ((tid & 31) == 0) { int w = tid >> 5; s0[w] = a0; s1[w] = a1; s2[w] = a2; }
    __syncthreads();
    if (tid == 0) {
        float l0 = s0[0] + s0[1] + s0[2] + s0[3] + lin2_b[0];
        float l1 = s1[0] + s1[1] + s1[2] + s1[3] + lin2_b[1];
        float l2 = s2[0] + s2[1] + s2[2] + s2[3] + lin2_b[2];
        float m = fmaxf(l0, fmaxf(l1, l2));
        float lse = logf(expf(l0 - m) + expf(l1 - m) + expf(l2 - m)) + m;
        out[b * NC_ + 0] = l0 - lse;
        out[b * NC_ + 1] = l1 - lse;
        out[b * NC_ + 2] = l2 - lse;
    }
}

// ---------------- launch ----------------
extern "C" void kernel_launch(void* const* d_in, const int* in_sizes, int n_in,
                              void* d_out, int out_size) {
    const float* token_feats = (const float*)d_in[0];
    const float* concat_cls  = (const float*)d_in[1];
    const float* W_rel1      = (const float*)d_in[2];
    const float* W_root1     = (const float*)d_in[3];
    const float* b1          = (const float*)d_in[4];
    const float* W_rel2      = (const float*)d_in[5];
    const float* W_root2     = (const float*)d_in[6];
    const float* b2          = (const float*)d_in[7];
    const float* att_w0      = (const float*)d_in[8];
    const float* att_w1      = (const float*)d_in[9];
    const float* lin1_w      = (const float*)d_in[10];
    const float* lin1_b      = (const float*)d_in[11];
    const float* lin2_w      = (const float*)d_in[12];
    const float* lin2_b      = (const float*)d_in[13];
    const int*   wti         = (const int*)d_in[14];
    const int*   eidx        = (const int*)d_in[15];
    const int*   etype       = (const int*)d_in[16];
    const int*   csi         = (const int*)d_in[17];
    float* out = (float*)d_out;

    float *p_ev, *p_attin, *p_hatt, *p_rep, *p_hid;
    int* p_cnt;
    uint32_t *p_hh, *p_xh, *p_yh, *p_bh1, *p_bh2;
    cudaGetSymbolAddress((void**)&p_cnt,   g_cnt);
    cudaGetSymbolAddress((void**)&p_ev,    g_ev);
    cudaGetSymbolAddress((void**)&p_attin, g_attin);
    cudaGetSymbolAddress((void**)&p_hatt,  g_hatt);
    cudaGetSymbolAddress((void**)&p_rep,   g_rep);
    cudaGetSymbolAddress((void**)&p_hid,   g_hid);
    cudaGetSymbolAddress((void**)&p_hh,    g_hh);
    cudaGetSymbolAddress((void**)&p_xh,    g_xh);
    cudaGetSymbolAddress((void**)&p_yh,    g_yh);
    cudaGetSymbolAddress((void**)&p_bh1,   g_bh1);
    cudaGetSymbolAddress((void**)&p_bh2,   g_bh2);

    cudaFuncSetAttribute(gemm_rgcn, cudaFuncAttributeMaxDynamicSharedMemorySize, GSMEM);

    const int T = 256;
    const long long NQ = (long long)NN_ * D2_;
    const int CVB = KP2_ * D_;
    const dim3 ggrid(D_ / GBN, NN_ / GBM);   // (3, 80)
    const int HKW = D_ + 2 * DOUT_;          // 2304

    // --- graph prep: CSR ---
    zero4_kernel<<<(NR_ / 4 + T - 1) / T, T>>>((float4*)p_cnt, NR_ / 4);
    count_kernel<<<(EE_ + T - 1) / T, T>>>(eidx, etype);
    scan_kernel<<<1, 1024>>>();
    scatter_kernel<<<(EE_ + T - 1) / T, T>>>(eidx, etype);

    // --- x0 + both weight conversions ---
    gather_mean_kernel<<<(unsigned)((NQ + T - 1) / T), T>>>(token_feats, wti);
    convertB_both_kernel<<<(CVB + T - 1) / T, T>>>(W_rel1, W_root1, W_rel2, W_root2);

    // --- layer 1 (fp16 -> fp16) ---
    csr_agg_kernel<<<NN_, 192>>>(p_xh);
    gemm_rgcn<<<ggrid, 256, GSMEM>>>(p_hh, p_xh, p_bh1, b1, p_yh, nullptr);

    // --- layer 2 (fp16 -> pooled ev directly) ---
    csr_agg_kernel<<<NN_, 192>>>(p_yh);
    gemm_rgcn<<<ggrid, 256, GSMEM>>>(p_hh, p_yh, p_bh2, b2, nullptr, p_ev);

    // --- attention head ---
    {
        int tot = SEQS_ * HKW + SEQS_ * DOUT_;
        attin_prep_kernel<<<(tot + T - 1) / T, T>>>(token_feats, csi);
    }
    {
        dim3 hg(DOUT_ / HB, (SEQS_ + HB - 1) / HB, 8);   // (12, 5, 8)
        sgemm_splitk<<<hg, 256>>>(p_attin, att_w0, p_hatt, SEQS_, DOUT_, HKW, HKW / 8);
    }
    dotp_softmax_kernel<<<B_, 256>>>(att_w1, out);

    // --- graph readout + classifier ---
    {
        int tot = B_ * HKW + B_ * LH_;
        rep_bias_kernel<<<(tot + T - 1) / T, T>>>(concat_cls, lin1_b);
    }
    {
        dim3 hg(LH_ / HB, (B_ + HB - 1) / HB, 8);        // (16, 1, 8)
        sgemm_splitk<<<hg, 256>>>(p_rep, lin1_w, p_hid, B_, LH_, HKW, HKW / 8);
    }
    final_kernel<<<B_, 128>>>(lin2_w, lin2_b, out);
}

// round 13
// speedup vs baseline: 3.2553x; 1.0563x over previous
#include <cuda_runtime.h>
#include <cuda_fp16.h>
#include <math.h>
#include <stdint.h>

// ---------------- problem constants ----------------
#define B_      64
#define EVI_    5
#define SEQS_   (B_ * EVI_)          // 320
#define L_      256
#define D_      768
#define D2_     (D_ / 2)             // 384 u32 per fp16-pair row
#define WORDS_  32
#define TPW_    4
#define NN_     (SEQS_ * WORDS_)     // 10240 nodes
#define EE_     (NN_ * 16)           // 163840 edges
#define R_      4
#define DOUT_   768
#define LH_     1024
#define NC_     3
#define KTOT_   (5 * D_)             // 3840 fused K
#define NR_     (NN_ * R_)           // 40960 segments
#define KP2_    (KTOT_ / 2)          // 1920 k-pairs

// ---------------- scratch (device globals; no allocs allowed) ----------------
__device__ uint32_t g_hh  [(size_t)R_ * NN_ * D2_];  // fp16 h, k-pair packed
__device__ uint32_t g_xh  [(size_t)NN_ * D2_];       // fp16 x0
__device__ uint32_t g_yh  [(size_t)NN_ * D2_];       // fp16 x1
__device__ uint32_t g_bh1 [(size_t)KP2_ * D_];       // fp16 Wcat layer 1
__device__ uint32_t g_bh2 [(size_t)KP2_ * D_];       // fp16 Wcat layer 2
__device__ int      g_cnt [NR_];
__device__ int      g_off [NR_ + 1];
__device__ int      g_cur [NR_];
__device__ int      g_elist[EE_];
__device__ float    g_ev  [SEQS_ * 2 * DOUT_];
__device__ float    g_attin[SEQS_ * (D_ + 2 * DOUT_)];
__device__ float    g_hatt[SEQS_ * DOUT_];
__device__ float    g_a   [SEQS_];
__device__ float    g_rep [B_ * (2 * DOUT_ + D_)];
__device__ float    g_hid [B_ * LH_];

// ---------------- small device helpers ----------------
__device__ __forceinline__ uint32_t smem_u32(const void* p) {
    uint32_t a;
    asm("{ .reg .u64 t; cvta.to.shared.u64 t, %1; cvt.u32.u64 %0, t; }" : "=r"(a) : "l"(p));
    return a;
}
__device__ __forceinline__ uint32_t packh2(float v0, float v1) {
    __half h0 = __float2half_rn(v0);
    __half h1 = __float2half_rn(v1);
    return ((uint32_t)__half_as_ushort(h1) << 16) | (uint32_t)__half_as_ushort(h0);
}
__device__ __forceinline__ float2 unpackh2(uint32_t u) {
    __half2 h = *(__half2*)&u;
    return __half22float2(h);
}
__device__ __forceinline__ void mma16816h(float* c, const uint32_t* a, const uint32_t* b) {
    asm volatile("mma.sync.aligned.m16n8k16.row.col.f32.f16.f16.f32 "
                 "{%0,%1,%2,%3}, {%4,%5,%6,%7}, {%8,%9}, {%0,%1,%2,%3};"
                 : "+f"(c[0]), "+f"(c[1]), "+f"(c[2]), "+f"(c[3])
                 : "r"(a[0]), "r"(a[1]), "r"(a[2]), "r"(a[3]), "r"(b[0]), "r"(b[1]));
}
__device__ __forceinline__ void cp16(uint32_t dst, const void* src) {
    asm volatile("cp.async.cg.shared.global [%0], [%1], 16;" :: "r"(dst), "l"(src));
}
__device__ __forceinline__ void red4(float* p, float a, float b, float c, float d) {
    asm volatile("red.global.add.v4.f32 [%0], {%1,%2,%3,%4};"
                 :: "l"(p), "f"(a), "f"(b), "f"(c), "f"(d) : "memory");
}

// ---------------- utility kernels ----------------
__global__ void zero4_kernel(float4* p, long long n4) {
    long long t = (long long)blockIdx.x * blockDim.x + threadIdx.x;
    if (t < n4) p[t] = make_float4(0.f, 0.f, 0.f, 0.f);
}

// ---------------- graph prep: counts -> scan -> scatter (CSR) ----------------
__global__ void count_kernel(const int* __restrict__ eidx, const int* __restrict__ etype) {
    int e = blockIdx.x * blockDim.x + threadIdx.x;
    if (e >= EE_) return;
    atomicAdd(&g_cnt[eidx[EE_ + e] * R_ + etype[e]], 1);
}
__global__ void scan_kernel() {
    __shared__ int part[1024];
    int tid = threadIdx.x;
    int base = tid * 40;
    int s = 0;
#pragma unroll 8
    for (int i = 0; i < 40; ++i) s += g_cnt[base + i];
    part[tid] = s;
    __syncthreads();
    for (int o = 1; o < 1024; o <<= 1) {
        int v = (tid >= o) ? part[tid - o] : 0;
        __syncthreads();
        part[tid] += v;
        __syncthreads();
    }
    int run = tid ? part[tid - 1] : 0;
#pragma unroll 8
    for (int i = 0; i < 40; ++i) {
        int c = g_cnt[base + i];
        g_off[base + i] = run;
        g_cur[base + i] = run;
        run += c;
    }
    if (tid == 1023) g_off[NR_] = run;
}
__global__ void scatter_kernel(const int* __restrict__ eidx, const int* __restrict__ etype) {
    int e = blockIdx.x * blockDim.x + threadIdx.x;
    if (e >= EE_) return;
    int pos = atomicAdd(&g_cur[eidx[EE_ + e] * R_ + etype[e]], 1);
    g_elist[pos] = eidx[e];
}

// x0 fp16 pack; thread owns a column pair
__global__ void gather_mean_kernel(const float* __restrict__ tok, const int* __restrict__ wti) {
    long long t = (long long)blockIdx.x * blockDim.x + threadIdx.x;
    if (t >= (long long)NN_ * D2_) return;
    int n = (int)(t / D2_);
    int d = (int)(t % D2_) * 2;
    const int* w = wti + n * TPW_;
    float v0 = 0.f, v1 = 0.f;
#pragma unroll
    for (int i = 0; i < TPW_; ++i) {
        const float* r = tok + (size_t)w[i] * D_ + d;
        v0 += r[0]; v1 += r[1];
    }
    g_xh[t] = packh2(v0 * 0.25f, v1 * 0.25f);
}

// grid (NN_, 2): CTA handles dst node, 2 relations; 192 threads, 2 u32 each.
// Edge loop unrolled 4-wide for MLP.
__global__ void __launch_bounds__(192)
csr_agg_kernel(const uint32_t* __restrict__ xh) {
    int dst = blockIdx.x;
    int q = threadIdx.x * 2;
#pragma unroll
    for (int rr = 0; rr < 2; ++rr) {
        int r = blockIdx.y * 2 + rr;
        int beg = g_off[dst * R_ + r];
        int end = g_off[dst * R_ + r + 1];
        float4 a = make_float4(0.f, 0.f, 0.f, 0.f);
        int i = beg;
        for (; i + 4 <= end; i += 4) {
            int s0 = g_elist[i], s1 = g_elist[i + 1], s2 = g_elist[i + 2], s3 = g_elist[i + 3];
            uint2 v0 = *(const uint2*)(xh + (size_t)s0 * D2_ + q);
            uint2 v1 = *(const uint2*)(xh + (size_t)s1 * D2_ + q);
            uint2 v2 = *(const uint2*)(xh + (size_t)s2 * D2_ + q);
            uint2 v3 = *(const uint2*)(xh + (size_t)s3 * D2_ + q);
            float2 f;
            f = unpackh2(v0.x); a.x += f.x; a.y += f.y;
            f = unpackh2(v0.y); a.z += f.x; a.w += f.y;
            f = unpackh2(v1.x); a.x += f.x; a.y += f.y;
            f = unpackh2(v1.y); a.z += f.x; a.w += f.y;
            f = unpackh2(v2.x); a.x += f.x; a.y += f.y;
            f = unpackh2(v2.y); a.z += f.x; a.w += f.y;
            f = unpackh2(v3.x); a.x += f.x; a.y += f.y;
            f = unpackh2(v3.y); a.z += f.x; a.w += f.y;
        }
        for (; i < end; ++i) {
            int src = g_elist[i];
            uint2 v = *(const uint2*)(xh + (size_t)src * D2_ + q);
            float2 f0 = unpackh2(v.x);
            float2 f1 = unpackh2(v.y);
            a.x += f0.x; a.y += f0.y; a.z += f1.x; a.w += f1.y;
        }
        float s = (end > beg) ? (1.f / (float)(end - beg)) : 0.f;
        size_t o = ((size_t)r * NN_ + dst) * D2_ + q;
        *(uint2*)&g_hh[o] = make_uint2(packh2(a.x * s, a.y * s), packh2(a.z * s, a.w * s));
    }
}

// both layers' Wcat -> fp16 k-pair packed
__global__ void convertB_both_kernel(const float* __restrict__ Wrel1, const float* __restrict__ Wroot1,
                                     const float* __restrict__ Wrel2, const float* __restrict__ Wroot2) {
    int t = blockIdx.x * blockDim.x + threadIdx.x;
    if (t >= KP2_ * D_) return;
    int k2 = t / D_;
    int n  = t - k2 * D_;
    int k  = 2 * k2;
    if (k < 4 * D_) {
        const float* b1 = Wrel1 + (size_t)k * D_ + n;
        const float* b2 = Wrel2 + (size_t)k * D_ + n;
        g_bh1[t] = packh2(b1[0], b1[D_]);
        g_bh2[t] = packh2(b2[0], b2[D_]);
    } else {
        const float* b1 = Wroot1 + (size_t)(k - 4 * D_) * D_ + n;
        const float* b2 = Wroot2 + (size_t)(k - 4 * D_) * D_ + n;
        g_bh1[t] = packh2(b1[0], b1[D_]);
        g_bh2[t] = packh2(b2[0], b2[D_]);
    }
}

// ---------------- fp16 single-pass tensor GEMM: 4-stage cp.async ring ----------------
// relu( [h0|h1|h2|h3|x] @ Wcat + bias ) -> fp16 Yh, or pooled mean|max -> Ev
#define GBM 128
#define GBN 256
#define GBK 32
#define NSTG (KTOT_ / GBK)   // 120
#define AP_  20
#define BP_  264
#define ASZ_ (GBM * AP_)     // 2560 u32
#define BSZ_ (16 * BP_)      // 4224 u32
#define SBUF (ASZ_ + BSZ_)   // 6784 u32 per stage
#define GSMEM (4 * SBUF * 4) // 108544 bytes

__global__ void __launch_bounds__(256, 1)
gemm_rgcn(const uint32_t* __restrict__ Hh, const uint32_t* __restrict__ Xh,
          const uint32_t* __restrict__ Bh,
          const float* __restrict__ bias,
          uint32_t* __restrict__ Yh, float* __restrict__ Ev) {
    extern __shared__ uint32_t sm[];
    const uint32_t sb = smem_u32(sm);
    const int tid  = threadIdx.x;
    const int wid  = tid >> 5;
    const int lane = tid & 31;
    const int g    = lane >> 2;
    const int tc   = lane & 3;
    const int wm   = wid & 3;        // 0..3 -> 32-row slice (one sequence)
    const int wn   = wid >> 2;       // 0..1 -> 128-col slice
    const int m0   = blockIdx.y * GBM;
    const int n0   = blockIdx.x * GBN;

    float acc[2][16][4];
#pragma unroll
    for (int i = 0; i < 2; ++i)
#pragma unroll
        for (int j = 0; j < 16; ++j)
#pragma unroll
            for (int q = 0; q < 4; ++q) acc[i][j][q] = 0.f;

    auto issueA = [&](int kc, int buf) {
        const int k0 = kc * GBK;
        const int r  = k0 / D_;
        const int dq = (k0 - r * D_) >> 1;
        const uint32_t* src = (r < 4) ? (Hh + ((size_t)r * NN_ + m0) * D2_ + dq)
                                      : (Xh + (size_t)m0 * D2_ + dq);
        const uint32_t aB = sb + (uint32_t)buf * (SBUF * 4);
#pragma unroll
        for (int i = 0; i < 2; ++i) {
            int c = tid + i * 256;
            int row = c >> 2, seg = c & 3;
            cp16(aB + row * (AP_ * 4) + seg * 16, src + (size_t)row * D2_ + seg * 4);
        }
    };
    auto issueB = [&](int kc, int buf) {
        const int kp0 = kc * 16;
        const uint32_t bbH = sb + (uint32_t)buf * (SBUF * 4) + ASZ_ * 4;
#pragma unroll
        for (int i = 0; i < 4; ++i) {
            int c = tid + i * 256;
            int row = c >> 6, seg = c & 63;
            size_t gidx = (size_t)(kp0 + row) * D_ + n0 + seg * 4;
            cp16(bbH + row * (BP_ * 4) + seg * 16, Bh + gidx);
        }
    };
    auto compute = [&](const uint32_t* s) {
        const uint32_t* AsH = s;
        const uint32_t* BsH = s + ASZ_;
#pragma unroll
        for (int ks = 0; ks < 2; ++ks) {
            const int kb = ks * 8;
            uint32_t aH[2][4];
#pragma unroll
            for (int mt = 0; mt < 2; ++mt) {
                int i0 = (wm * 32 + mt * 16 + g) * AP_ + kb + tc;
                int i1 = i0 + 8 * AP_;
                aH[mt][0] = AsH[i0]; aH[mt][1] = AsH[i1];
                aH[mt][2] = AsH[i0 + 4]; aH[mt][3] = AsH[i1 + 4];
            }
#pragma unroll
            for (int ng = 0; ng < 4; ++ng) {
                uint32_t bh[4][2];
#pragma unroll
                for (int q = 0; q < 4; ++q) {
                    int cb = wn * 128 + (ng * 4 + q) * 8;
                    int j0 = (kb + tc) * BP_ + cb + g;
                    int j1 = j0 + 4 * BP_;
                    bh[q][0] = BsH[j0]; bh[q][1] = BsH[j1];
                }
#pragma unroll
                for (int mt = 0; mt < 2; ++mt)
#pragma unroll
                    for (int q = 0; q < 4; ++q)
                        mma16816h(acc[mt][ng * 4 + q], aH[mt], bh[q]);
            }
        }
    };

    issueA(0, 0); issueB(0, 0);
    asm volatile("cp.async.commit_group;" ::: "memory");
    issueA(1, 1); issueB(1, 1);
    asm volatile("cp.async.commit_group;" ::: "memory");

#pragma unroll 1
    for (int kc = 0; kc < NSTG; ++kc) {
        if (kc + 2 < NSTG) {
            int buf = (kc + 2) & 3;
            issueA(kc + 2, buf);
            issueB(kc + 2, buf);
            asm volatile("cp.async.commit_group;" ::: "memory");
            asm volatile("cp.async.wait_group 2;" ::: "memory");
        } else if (kc + 1 < NSTG) {
            asm volatile("cp.async.wait_group 1;" ::: "memory");
        } else {
            asm volatile("cp.async.wait_group 0;" ::: "memory");
        }
        __syncthreads();
        compute(sm + (uint32_t)(kc & 3) * SBUF);
    }

    if (Ev) {
        // ---- pooled epilogue: bias+relu, mean/max over the 32 words (this warp's rows) ----
        const int seq = blockIdx.y * 4 + wm;
#pragma unroll
        for (int nt = 0; nt < 16; ++nt) {
            int col = n0 + wn * 128 + nt * 8 + tc * 2;
            float b0 = __ldg(bias + col);
            float b1 = __ldg(bias + col + 1);
            float s0 = 0.f, s1 = 0.f, x0 = 0.f, x1 = 0.f;
#pragma unroll
            for (int mt = 0; mt < 2; ++mt) {
                float v;
                v = fmaxf(acc[mt][nt][0] + b0, 0.f); s0 += v; x0 = fmaxf(x0, v);
                v = fmaxf(acc[mt][nt][2] + b0, 0.f); s0 += v; x0 = fmaxf(x0, v);
                v = fmaxf(acc[mt][nt][1] + b1, 0.f); s1 += v; x1 = fmaxf(x1, v);
                v = fmaxf(acc[mt][nt][3] + b1, 0.f); s1 += v; x1 = fmaxf(x1, v);
            }
#pragma unroll
            for (int off = 4; off <= 16; off <<= 1) {
                s0 += __shfl_xor_sync(0xffffffffu, s0, off);
                s1 += __shfl_xor_sync(0xffffffffu, s1, off);
                x0 = fmaxf(x0, __shfl_xor_sync(0xffffffffu, x0, off));
                x1 = fmaxf(x1, __shfl_xor_sync(0xffffffffu, x1, off));
            }
            if (lane < 4) {
                float* evr = Ev + (size_t)seq * (2 * DOUT_);
                evr[col]             = s0 * (1.f / WORDS_);
                evr[col + 1]         = s1 * (1.f / WORDS_);
                evr[DOUT_ + col]     = x0;
                evr[DOUT_ + col + 1] = x1;
            }
        }
    } else {
        // ---- standard epilogue: bias + relu -> fp16 ----
#pragma unroll
        for (int mt = 0; mt < 2; ++mt) {
            int row = m0 + wm * 32 + mt * 16 + g;
#pragma unroll
            for (int nt = 0; nt < 16; ++nt) {
                int col = n0 + wn * 128 + nt * 8 + tc * 2;
                float b0 = __ldg(bias + col);
                float b1 = __ldg(bias + col + 1);
                float2 v0 = make_float2(fmaxf(acc[mt][nt][0] + b0, 0.f),
                                        fmaxf(acc[mt][nt][1] + b1, 0.f));
                float2 v1 = make_float2(fmaxf(acc[mt][nt][2] + b0, 0.f),
                                        fmaxf(acc[mt][nt][3] + b1, 0.f));
                Yh[(size_t)row * D2_ + (col >> 1)]       = packh2(v0.x, v0.y);
                Yh[(size_t)(row + 8) * D2_ + (col >> 1)] = packh2(v1.x, v1.y);
            }
        }
    }
}

// ---------------- split-K fp32 GEMM for head ops ----------------
#define HB 64
#define HK 16
__global__ void __launch_bounds__(256)
sgemm_splitk(const float* __restrict__ A, const float* __restrict__ Bm,
             float* __restrict__ C, int M, int N, int K, int kchunk) {
    __shared__ float As[HK][HB + 4];
    __shared__ float Bs[HK][HB + 4];
    const int tid = threadIdx.x;
    const int tr = tid >> 4;
    const int tcol = tid & 15;
    const int m0 = blockIdx.y * HB;
    const int n0 = blockIdx.x * HB;
    const int k0 = blockIdx.z * kchunk;
    const int ar = tid >> 2, ac = (tid & 3) * 4;
    const int br = tid >> 4, bc = (tid & 15) * 4;
    float acc[4][4] = {};
    for (int kk = 0; kk < kchunk; kk += HK) {
        int k = k0 + kk;
        float4 av = (m0 + ar < M) ? *(const float4*)(A + (size_t)(m0 + ar) * K + k + ac)
                                  : make_float4(0.f, 0.f, 0.f, 0.f);
        As[ac + 0][ar] = av.x;
        As[ac + 1][ar] = av.y;
        As[ac + 2][ar] = av.z;
        As[ac + 3][ar] = av.w;
        *(float4*)&Bs[br][bc] = *(const float4*)(Bm + (size_t)(k + br) * N + n0 + bc);
        __syncthreads();
#pragma unroll
        for (int kq = 0; kq < HK; ++kq) {
            float rm[4], rn[4];
#pragma unroll
            for (int i = 0; i < 4; ++i) rm[i] = As[kq][tr * 4 + i];
#pragma unroll
            for (int j = 0; j < 4; ++j) rn[j] = Bs[kq][tcol * 4 + j];
#pragma unroll
            for (int i = 0; i < 4; ++i)
#pragma unroll
                for (int j = 0; j < 4; ++j)
                    acc[i][j] += rm[i] * rn[j];
        }
        __syncthreads();
    }
#pragma unroll
    for (int i = 0; i < 4; ++i) {
        int row = m0 + tr * 4 + i;
        if (row < M)
            red4(C + (size_t)row * N + n0 + tcol * 4,
                 acc[i][0], acc[i][1], acc[i][2], acc[i][3]);
    }
}

// ---------------- fused head kernels ----------------
__global__ void attin_prep_kernel(const float* __restrict__ tok, const int* __restrict__ csi) {
    int t = blockIdx.x * blockDim.x + threadIdx.x;
    const int W = D_ + 2 * DOUT_;
    const int NA = SEQS_ * W;
    if (t < NA) {
        int s = t / W, c = t % W;
        if (c < D_) {
            int seq = csi[s / EVI_];
            g_attin[t] = tok[(size_t)seq * L_ * D_ + c];
        } else {
            g_attin[t] = g_ev[s * (2 * DOUT_) + (c - D_)];
        }
    } else {
        int u = t - NA;
        if (u < SEQS_ * DOUT_) g_hatt[u] = 0.f;
    }
}
__global__ void dotp_softmax_kernel(const float* __restrict__ att_w1, float* __restrict__ out) {
    int b = blockIdx.x;
    int tid = threadIdx.x;
    __shared__ float red[8];
    __shared__ float pv[EVI_];
#pragma unroll
    for (int e = 0; e < EVI_; ++e) {
        int s = b * EVI_ + e;
        float acc = 0.f;
        for (int k = tid; k < DOUT_; k += 256)
            acc += fmaxf(g_hatt[(size_t)s * DOUT_ + k], 0.f) * att_w1[k];
#pragma unroll
        for (int o = 16; o; o >>= 1) acc += __shfl_down_sync(0xffffffffu, acc, o);
        if ((tid & 31) == 0) red[tid >> 5] = acc;
        __syncthreads();
        if (tid == 0) {
            float r = 0.f;
#pragma unroll
            for (int w = 0; w < 8; ++w) r += red[w];
            pv[e] = r;
        }
        __syncthreads();
    }
    if (tid == 0) {
        float m = -1e30f;
#pragma unroll
        for (int e = 0; e < EVI_; ++e) m = fmaxf(m, pv[e]);
        float s = 0.f;
        float ex[EVI_];
#pragma unroll
        for (int e = 0; e < EVI_; ++e) { ex[e] = expf(pv[e] - m); s += ex[e]; }
        float is = 1.f / s;
#pragma unroll
        for (int e = 0; e < EVI_; ++e) {
            g_a[b * EVI_ + e] = ex[e] * is;
            out[B_ * NC_ + b * EVI_ + e] = 1.f / (1.f + expf(-pv[e]));
        }
    }
}
__global__ void rep_bias_kernel(const float* __restrict__ concat_cls, const float* __restrict__ lin1_b) {
    int t = blockIdx.x * blockDim.x + threadIdx.x;
    const int W = 2 * DOUT_ + D_;
    const int NR = B_ * W;
    if (t < NR) {
        int b = t / W, c = t % W;
        if (c < 2 * DOUT_) {
            float acc = 0.f;
#pragma unroll
            for (int e = 0; e < EVI_; ++e)
                acc += g_a[b * EVI_ + e] * g_ev[(size_t)(b * EVI_ + e) * (2 * DOUT_) + c];
            g_rep[t] = acc;
        } else {
            g_rep[t] = concat_cls[b * D_ + (c - 2 * DOUT_)];
        }
    } else {
        int u = t - NR;
        if (u < B_ * LH_) g_hid[u] = lin1_b[u % LH_];
    }
}
__global__ void final_kernel(const float* __restrict__ lin2_w,
                             const float* __restrict__ lin2_b,
                             float* __restrict__ out) {
    int b = blockIdx.x;
    int tid = threadIdx.x;
    float a0 = 0.f, a1 = 0.f, a2 = 0.f;
    for (int k = tid; k < LH_; k += 128) {
        float h = fmaxf(g_hid[(size_t)b * LH_ + k], 0.f);
        a0 += h * lin2_w[k * NC_ + 0];
        a1 += h * lin2_w[k * NC_ + 1];
        a2 += h * lin2_w[k * NC_ + 2];
    }
#pragma unroll
    for (int o = 16; o; o >>= 1) {
        a0 += __shfl_down_sync(0xffffffffu, a0, o);
        a1 += __shfl_down_sync(0xffffffffu, a1, o);
        a2 += __shfl_down_sync(0xffffffffu, a2, o);
    }
    __shared__ float s0[4], s1[4], s2[4];
    if ((tid & 31) == 0) { int w = tid >> 5; s0[w] = a0; s1[w] = a1; s2[w] = a2; }
    __syncthreads();
    if (tid == 0) {
        float l0 = s0[0] + s0[1] + s0[2] + s0[3] + lin2_b[0];
        float l1 = s1[0] + s1[1] + s1[2] + s1[3] + lin2_b[1];
        float l2 = s2[0] + s2[1] + s2[2] + s2[3] + lin2_b[2];
        float m = fmaxf(l0, fmaxf(l1, l2));
        float lse = logf(expf(l0 - m) + expf(l1 - m) + expf(l2 - m)) + m;
        out[b * NC_ + 0] = l0 - lse;
        out[b * NC_ + 1] = l1 - lse;
        out[b * NC_ + 2] = l2 - lse;
    }
}

// ---------------- launch ----------------
extern "C" void kernel_launch(void* const* d_in, const int* in_sizes, int n_in,
                              void* d_out, int out_size) {
    const float* token_feats = (const float*)d_in[0];
    const float* concat_cls  = (const float*)d_in[1];
    const float* W_rel1      = (const float*)d_in[2];
    const float* W_root1     = (const float*)d_in[3];
    const float* b1          = (const float*)d_in[4];
    const float* W_rel2      = (const float*)d_in[5];
    const float* W_root2     = (const float*)d_in[6];
    const float* b2          = (const float*)d_in[7];
    const float* att_w0      = (const float*)d_in[8];
    const float* att_w1      = (const float*)d_in[9];
    const float* lin1_w      = (const float*)d_in[10];
    const float* lin1_b      = (const float*)d_in[11];
    const float* lin2_w      = (const float*)d_in[12];
    const float* lin2_b      = (const float*)d_in[13];
    const int*   wti         = (const int*)d_in[14];
    const int*   eidx        = (const int*)d_in[15];
    const int*   etype       = (const int*)d_in[16];
    const int*   csi         = (const int*)d_in[17];
    float* out = (float*)d_out;

    float *p_ev, *p_attin, *p_hatt, *p_rep, *p_hid;
    int* p_cnt;
    uint32_t *p_hh, *p_xh, *p_yh, *p_bh1, *p_bh2;
    cudaGetSymbolAddress((void**)&p_cnt,   g_cnt);
    cudaGetSymbolAddress((void**)&p_ev,    g_ev);
    cudaGetSymbolAddress((void**)&p_attin, g_attin);
    cudaGetSymbolAddress((void**)&p_hatt,  g_hatt);
    cudaGetSymbolAddress((void**)&p_rep,   g_rep);
    cudaGetSymbolAddress((void**)&p_hid,   g_hid);
    cudaGetSymbolAddress((void**)&p_hh,    g_hh);
    cudaGetSymbolAddress((void**)&p_xh,    g_xh);
    cudaGetSymbolAddress((void**)&p_yh,    g_yh);
    cudaGetSymbolAddress((void**)&p_bh1,   g_bh1);
    cudaGetSymbolAddress((void**)&p_bh2,   g_bh2);

    cudaFuncSetAttribute(gemm_rgcn, cudaFuncAttributeMaxDynamicSharedMemorySize, GSMEM);

    const int T = 256;
    const long long NQ = (long long)NN_ * D2_;
    const int CVB = KP2_ * D_;
    const dim3 ggrid(D_ / GBN, NN_ / GBM);   // (3, 80)
    const dim3 agrid(NN_, 2);
    const int HKW = D_ + 2 * DOUT_;          // 2304

    // --- graph prep: CSR ---
    zero4_kernel<<<(NR_ / 4 + T - 1) / T, T>>>((float4*)p_cnt, NR_ / 4);
    count_kernel<<<(EE_ + T - 1) / T, T>>>(eidx, etype);
    scan_kernel<<<1, 1024>>>();
    scatter_kernel<<<(EE_ + T - 1) / T, T>>>(eidx, etype);

    // --- x0 + both weight conversions ---
    gather_mean_kernel<<<(unsigned)((NQ + T - 1) / T), T>>>(token_feats, wti);
    convertB_both_kernel<<<(CVB + T - 1) / T, T>>>(W_rel1, W_root1, W_rel2, W_root2);

    // --- layer 1 (fp16 -> fp16) ---
    csr_agg_kernel<<<agrid, 192>>>(p_xh);
    gemm_rgcn<<<ggrid, 256, GSMEM>>>(p_hh, p_xh, p_bh1, b1, p_yh, nullptr);

    // --- layer 2 (fp16 -> pooled ev directly) ---
    csr_agg_kernel<<<agrid, 192>>>(p_yh);
    gemm_rgcn<<<ggrid, 256, GSMEM>>>(p_hh, p_yh, p_bh2, b2, nullptr, p_ev);

    // --- attention head ---
    {
        int tot = SEQS_ * HKW + SEQS_ * DOUT_;
        attin_prep_kernel<<<(tot + T - 1) / T, T>>>(token_feats, csi);
    }
    {
        dim3 hg(DOUT_ / HB, (SEQS_ + HB - 1) / HB, 8);   // (12, 5, 8)
        sgemm_splitk<<<hg, 256>>>(p_attin, att_w0, p_hatt, SEQS_, DOUT_, HKW, HKW / 8);
    }
    dotp_softmax_kernel<<<B_, 256>>>(att_w1, out);

    // --- graph readout + classifier ---
    {
        int tot = B_ * HKW + B_ * LH_;
        rep_bias_kernel<<<(tot + T - 1) / T, T>>>(concat_cls, lin1_b);
    }
    {
        dim3 hg(LH_ / HB, (B_ + HB - 1) / HB, 8);        // (16, 1, 8)
        sgemm_splitk<<<hg, 256>>>(p_rep, lin1_w, p_hid, B_, LH_, HKW, HKW / 8);
    }
    final_kernel<<<B_, 128>>>(lin2_w, lin2_b, out);
}